// round 6
// baseline (speedup 1.0000x reference)
#include <cuda_runtime.h>
#include <cuda_bf16.h>
#include <cstdint>
#include <math.h>

#define SQ     2048
#define DMODEL 1024
#define NH     16
#define DH     64
#define BMAX   2
#define MMAX   (BMAX * SQ)          // 4096

// ---------------- scratch (__device__ globals, allocation-free) -------------
__device__ __nv_bfloat16  g_qkvhi[3 * MMAX * DMODEL];   // q|k|v hi planes
__device__ __nv_bfloat16  g_qkvlo[3 * MMAX * DMODEL];   // q|k|v lo planes
__device__ __nv_bfloat16  g_ahi[MMAX * DMODEL];         // x split / attn-out split
__device__ __nv_bfloat16  g_alo[MMAX * DMODEL];
__device__ __nv_bfloat16  g_whi[3 * DMODEL * DMODEL];   // weights [N][K]
__device__ __nv_bfloat16  g_wlo[3 * DMODEL * DMODEL];
__device__ float          g_bias[3 * DMODEL];

// ---------------------------------------------------------------------------
__device__ __forceinline__ void bsplit(float x, __nv_bfloat16& h, __nv_bfloat16& l)
{
    h = __float2bfloat16_rn(x);
    l = __float2bfloat16_rn(x - __bfloat162float(h));
}

__device__ __forceinline__ void bpack2(float a, float b, uint32_t& hi, uint32_t& lo)
{
    __nv_bfloat16 ha = __float2bfloat16_rn(a), hb = __float2bfloat16_rn(b);
    __nv_bfloat162 H; H.x = ha; H.y = hb;
    __nv_bfloat162 L;
    L.x = __float2bfloat16_rn(a - __bfloat162float(ha));
    L.y = __float2bfloat16_rn(b - __bfloat162float(hb));
    hi = reinterpret_cast<uint32_t&>(H);
    lo = reinterpret_cast<uint32_t&>(L);
}

#define LDSM4(r, a)                                                            \
    asm volatile("ldmatrix.sync.aligned.m8n8.x4.shared.b16 {%0,%1,%2,%3},[%4];"\
                 : "=r"((r)[0]), "=r"((r)[1]), "=r"((r)[2]), "=r"((r)[3])      \
                 : "r"(a))
#define LDSM4T(r, a)                                                           \
    asm volatile("ldmatrix.sync.aligned.m8n8.x4.trans.shared.b16 "             \
                 "{%0,%1,%2,%3},[%4];"                                         \
                 : "=r"((r)[0]), "=r"((r)[1]), "=r"((r)[2]), "=r"((r)[3])      \
                 : "r"(a))
#define MMA16816(d, a, b0, b1)                                                 \
    asm volatile("mma.sync.aligned.m16n8k16.row.col.f32.bf16.bf16.f32 "        \
                 "{%0,%1,%2,%3},{%4,%5,%6,%7},{%8,%9},{%0,%1,%2,%3};"          \
                 : "+f"((d)[0]), "+f"((d)[1]), "+f"((d)[2]), "+f"((d)[3])      \
                 : "r"((a)[0]), "r"((a)[1]), "r"((a)[2]), "r"((a)[3]),         \
                   "r"(b0), "r"(b1))
#define CP16(dst, src)                                                         \
    asm volatile("cp.async.cg.shared.global [%0],[%1],16;"                     \
                 :: "r"(dst), "l"(src))
#define CP_COMMIT  asm volatile("cp.async.commit_group;")
#define CP_WAIT(n) asm volatile("cp.async.wait_group %0;" :: "n"(n))

// ---------------------------------------------------------------------------
__global__ void split_kernel(const float* __restrict__ in,
                             __nv_bfloat16* __restrict__ hi,
                             __nv_bfloat16* __restrict__ lo, int n4)
{
    int i = blockIdx.x * blockDim.x + threadIdx.x;
    if (i >= n4) return;
    float4 v = ((const float4*)in)[i];
    __nv_bfloat16 h0, h1, h2, h3, l0, l1, l2, l3;
    bsplit(v.x, h0, l0); bsplit(v.y, h1, l1);
    bsplit(v.z, h2, l2); bsplit(v.w, h3, l3);
    ushort4 hv = make_ushort4(__bfloat16_as_ushort(h0), __bfloat16_as_ushort(h1),
                              __bfloat16_as_ushort(h2), __bfloat16_as_ushort(h3));
    ushort4 lv = make_ushort4(__bfloat16_as_ushort(l0), __bfloat16_as_ushort(l1),
                              __bfloat16_as_ushort(l2), __bfloat16_as_ushort(l3));
    ((ushort4*)hi)[i] = hv;
    ((ushort4*)lo)[i] = lv;
}

__global__ void conv_wqkv_kernel(const float* __restrict__ wq, const float* __restrict__ wk,
                                 const float* __restrict__ wv, const float* __restrict__ bq,
                                 const float* __restrict__ bk, const float* __restrict__ bv,
                                 __nv_bfloat16* __restrict__ Whi,
                                 __nv_bfloat16* __restrict__ Wlo,
                                 float* __restrict__ gbias)
{
    int gt = blockIdx.x * 256 + threadIdx.x;
    int n  = gt >> 7;
    int d0 = (gt & 127) << 3;
    const float* w  = (n < 1024) ? wq : (n < 2048 ? wk : wv);
    const float* bb = (n < 1024) ? bq : (n < 2048 ? bk : bv);
    int nn = n & 1023, h = nn >> 6, e = nn & 63;
    const float* src = w + h * (DMODEL * DH) + e;

    __nv_bfloat16 hi[8], lo[8];
#pragma unroll
    for (int i = 0; i < 8; i++)
        bsplit(src[(size_t)(d0 + i) * DH], hi[i], lo[i]);

    size_t o = (size_t)n * DMODEL + d0;
    *(uint4*)(Whi + o) = *(const uint4*)hi;
    *(uint4*)(Wlo + o) = *(const uint4*)lo;
    if (d0 == 0) gbias[n] = bb[nn];
}

__global__ void conv_wo_kernel(const float* __restrict__ wo,
                               __nv_bfloat16* __restrict__ Whi,
                               __nv_bfloat16* __restrict__ Wlo)
{
    int gt = blockIdx.x * 256 + threadIdx.x;
    int n  = gt >> 7;
    int d0 = (gt & 127) << 3;
    __nv_bfloat16 hi[8], lo[8];
#pragma unroll
    for (int i = 0; i < 8; i++)
        bsplit(wo[(size_t)(d0 + i) * DMODEL + n], hi[i], lo[i]);
    size_t o = (size_t)n * DMODEL + d0;
    *(uint4*)(Whi + o) = *(const uint4*)hi;
    *(uint4*)(Wlo + o) = *(const uint4*)lo;
}

// ---------------------------------------------------------------------------
// Tensor-core GEMM, bf16 x3 split, cp.async 2-stage pipeline.
// ---------------------------------------------------------------------------
__global__ __launch_bounds__(256)
void gemm_bf16_split(const __nv_bfloat16* __restrict__ Ahi,
                     const __nv_bfloat16* __restrict__ Alo,
                     const __nv_bfloat16* __restrict__ Whi,
                     const __nv_bfloat16* __restrict__ Wlo,
                     const float* __restrict__ bias,
                     float* __restrict__ C,
                     __nv_bfloat16* __restrict__ Chi,
                     __nv_bfloat16* __restrict__ Clo, int M)
{
    __shared__ __align__(16) __nv_bfloat16 As[2][128][40];
    __shared__ __align__(16) __nv_bfloat16 Bs[2][128][40];
    const uint32_t STG = 128 * 40 * 2;          // stage stride bytes

    const int tid  = threadIdx.x;
    const int lane = tid & 31;
    const int wid  = tid >> 5;
    const int wm   = (wid & 3) * 32;
    const int wn   = (wid >> 2) * 64;
    const int m0   = blockIdx.y * 128;
    const int n0   = blockIdx.x * 128;

    const int lrow = tid >> 2;
    const int lcol = (tid & 3) * 8;

    float acc[2][8][4];
#pragma unroll
    for (int i = 0; i < 2; i++)
#pragma unroll
        for (int j = 0; j < 8; j++)
#pragma unroll
            for (int c = 0; c < 4; c++) acc[i][j][c] = 0.f;

    uint32_t a_addr[2], b_addr[4];
#pragma unroll
    for (int mi = 0; mi < 2; mi++)
        a_addr[mi] = (uint32_t)__cvta_generic_to_shared(
            &As[0][wm + mi * 16 + (lane & 15)][(lane >> 4) * 8]);
#pragma unroll
    for (int np = 0; np < 4; np++) {
        int g = lane >> 3, r = lane & 7;
        b_addr[np] = (uint32_t)__cvta_generic_to_shared(
            &Bs[0][wn + np * 16 + (g >> 1) * 8 + r][(g & 1) * 8]);
    }
    const uint32_t as_dst = (uint32_t)__cvta_generic_to_shared(&As[0][lrow][lcol]);
    const uint32_t bs_dst = (uint32_t)__cvta_generic_to_shared(&Bs[0][lrow][lcol]);
    const uint32_t row64  = 64 * 40 * 2;         // +64 rows in bytes

    // issue loads for K-block blk into stage blk&1
    auto issue = [&](int blk) {
        int p  = blk >> 5;
        int k0 = (blk & 31) << 5;
        const __nv_bfloat16* Ap = (p == 1) ? Alo : Ahi;
        const __nv_bfloat16* Wp = (p == 2) ? Wlo : Whi;
        const __nv_bfloat16* ag = Ap + (size_t)(m0 + lrow) * DMODEL + lcol + k0;
        const __nv_bfloat16* bg = Wp + (size_t)(n0 + lrow) * DMODEL + lcol + k0;
        uint32_t so = (blk & 1) * STG;
        CP16(as_dst + so,         ag);
        CP16(as_dst + so + row64, ag + (size_t)64 * DMODEL);
        CP16(bs_dst + so,         bg);
        CP16(bs_dst + so + row64, bg + (size_t)64 * DMODEL);
        CP_COMMIT;
    };

    issue(0);
    issue(1);

    for (int blk = 0; blk < 96; blk++) {
        if (blk == 95) { CP_WAIT(0); } else { CP_WAIT(1); }
        __syncthreads();

        const uint32_t so = (blk & 1) * STG;
#pragma unroll
        for (int ks = 0; ks < 32; ks += 16) {
            uint32_t af[2][4];
#pragma unroll
            for (int mi = 0; mi < 2; mi++)
                LDSM4(af[mi], a_addr[mi] + so + ks * 2);
#pragma unroll
            for (int np = 0; np < 4; np++) {
                uint32_t bf[4];
                LDSM4(bf, b_addr[np] + so + ks * 2);
#pragma unroll
                for (int mi = 0; mi < 2; mi++) {
                    MMA16816(acc[mi][np * 2],     af[mi], bf[0], bf[1]);
                    MMA16816(acc[mi][np * 2 + 1], af[mi], bf[2], bf[3]);
                }
            }
        }
        __syncthreads();
        if (blk + 2 < 96) issue(blk + 2);
    }

    const size_t plane = (size_t)M * DMODEL;
#pragma unroll
    for (int mi = 0; mi < 2; mi++) {
        int row = m0 + wm + mi * 16 + (lane >> 2);
#pragma unroll
        for (int ni = 0; ni < 8; ni++) {
            int col = n0 + wn + ni * 8 + (lane & 3) * 2;
            float b0 = bias ? bias[col]     : 0.f;
            float b1 = bias ? bias[col + 1] : 0.f;
            float v0 = acc[mi][ni][0] + b0, v1 = acc[mi][ni][1] + b1;
            float v2 = acc[mi][ni][2] + b0, v3 = acc[mi][ni][3] + b1;
            size_t o = (size_t)(col >> 10) * plane
                     + (size_t)row * DMODEL + (col & 1023);
            if (Chi) {
                uint32_t h01, l01, h23, l23;
                bpack2(v0, v1, h01, l01);
                bpack2(v2, v3, h23, l23);
                *(uint32_t*)(Chi + o)               = h01;
                *(uint32_t*)(Clo + o)               = l01;
                *(uint32_t*)(Chi + o + 8 * DMODEL)  = h23;
                *(uint32_t*)(Clo + o + 8 * DMODEL)  = l23;
            } else {
                *(float2*)(C + o)              = make_float2(v0, v1);
                *(float2*)(C + o + 8 * DMODEL) = make_float2(v2, v3);
            }
        }
    }
}

// ---------------------------------------------------------------------------
// Tensor-core flash attention, 2-stage cp.async K/V pipeline (dynamic smem).
// Stage layout (bytes): Kh[0..9216) Kl Vh Vl, each 64x72 bf16; stage=36864.
// ---------------------------------------------------------------------------
#define ATTN_STAGE 36864
#define OFF_KH 0
#define OFF_KL 9216
#define OFF_VH 18432
#define OFF_VL 27648

extern __shared__ __align__(16) char dynsm[];

__global__ __launch_bounds__(128)
void attn_tc_kernel(const __nv_bfloat16* __restrict__ Phi,
                    const __nv_bfloat16* __restrict__ Plo,
                    __nv_bfloat16* __restrict__ Ohi,
                    __nv_bfloat16* __restrict__ Olo)
{
    const int tid  = threadIdx.x;
    const int lane = tid & 31;
    const int w    = tid >> 5;
    const int hh   = blockIdx.y;
    const int b    = blockIdx.z;
    const int q0   = blockIdx.x * 64;

    const size_t plane = (size_t)gridDim.z * SQ * DMODEL;
    const __nv_bfloat16* Qh = Phi;
    const __nv_bfloat16* Ql = Plo;
    const __nv_bfloat16* Kh = Phi + plane;
    const __nv_bfloat16* Kl = Plo + plane;
    const __nv_bfloat16* Vh = Phi + 2 * plane;
    const __nv_bfloat16* Vl = Plo + 2 * plane;

    const int ldr = tid >> 1;
    const int ldc = (tid & 1) * 32;
    const size_t gb = ((size_t)b * SQ) * DMODEL + hh * DH;

    const uint32_t sb = (uint32_t)__cvta_generic_to_shared(dynsm);
    const uint32_t ld_off = (uint32_t)(ldr * 72 + ldc) * 2;

    // ---- stage Q into stage0 K region, extract frags ----
    {
        const __nv_bfloat16* sh = Qh + gb + (size_t)(q0 + ldr) * DMODEL + ldc;
        const __nv_bfloat16* sl = Ql + gb + (size_t)(q0 + ldr) * DMODEL + ldc;
        __nv_bfloat16* dh = (__nv_bfloat16*)(dynsm + OFF_KH) + ldr * 72 + ldc;
        __nv_bfloat16* dl = (__nv_bfloat16*)(dynsm + OFF_KL) + ldr * 72 + ldc;
#pragma unroll
        for (int i = 0; i < 4; i++) {
            *(uint4*)(dh + 8 * i) = *(const uint4*)(sh + 8 * i);
            *(uint4*)(dl + 8 * i) = *(const uint4*)(sl + 8 * i);
        }
    }
    __syncthreads();
    uint32_t qh[4][4], ql[4][4];
    {
        uint32_t qa = sb + OFF_KH + (uint32_t)((16 * w + (lane & 15)) * 72 + (lane >> 4) * 8) * 2;
        uint32_t qb = sb + OFF_KL + (uint32_t)((16 * w + (lane & 15)) * 72 + (lane >> 4) * 8) * 2;
#pragma unroll
        for (int t = 0; t < 4; t++) {
            LDSM4(qh[t], qa + t * 32);
            LDSM4(ql[t], qb + t * 32);
        }
    }
    __syncthreads();

    const uint32_t ka_h = sb + OFF_KH + (uint32_t)((lane & 7) * 72 + (lane >> 3) * 8) * 2;
    const uint32_t ka_l = sb + OFF_KL + (uint32_t)((lane & 7) * 72 + (lane >> 3) * 8) * 2;
    const uint32_t va_h = sb + OFF_VH + (uint32_t)(lane * 72) * 2;
    const uint32_t va_l = sb + OFF_VL + (uint32_t)(lane * 72) * 2;

    // issue K/V tile loads for iteration it into stage it&1
    auto issueKV = [&](int it) {
        const int kt = it * 64;
        const __nv_bfloat16* gkh = Kh + gb + (size_t)(kt + ldr) * DMODEL + ldc;
        const __nv_bfloat16* gkl = Kl + gb + (size_t)(kt + ldr) * DMODEL + ldc;
        const __nv_bfloat16* gvh = Vh + gb + (size_t)(kt + ldr) * DMODEL + ldc;
        const __nv_bfloat16* gvl = Vl + gb + (size_t)(kt + ldr) * DMODEL + ldc;
        uint32_t s = sb + (it & 1) * ATTN_STAGE + ld_off;
#pragma unroll
        for (int i = 0; i < 4; i++) {
            CP16(s + OFF_KH + 16 * i, gkh + 8 * i);
            CP16(s + OFF_KL + 16 * i, gkl + 8 * i);
            CP16(s + OFF_VH + 16 * i, gvh + 8 * i);
            CP16(s + OFF_VL + 16 * i, gvl + 8 * i);
        }
        CP_COMMIT;
    };

    float oacc[8][4];
#pragma unroll
    for (int i = 0; i < 8; i++)
#pragma unroll
        for (int c = 0; c < 4; c++) oacc[i][c] = 0.f;
    float mrow[2] = {-1e30f, -1e30f};
    float lsum[2] = {0.f, 0.f};

    issueKV(0);
    issueKV(1);

    for (int it = 0; it < SQ / 64; it++) {
        if (it == SQ / 64 - 1) { CP_WAIT(0); } else { CP_WAIT(1); }
        __syncthreads();
        const uint32_t so = (it & 1) * ATTN_STAGE;

        // ---- S = Q K^T, 3-pass split ----
        float sacc[8][4];
#pragma unroll
        for (int nf = 0; nf < 8; nf++) {
#pragma unroll
            for (int c = 0; c < 4; c++) sacc[nf][c] = 0.f;
            uint32_t bh[8], bl[8];
            LDSM4(&bh[0], ka_h + so + nf * 1152);
            LDSM4(&bh[4], ka_h + so + nf * 1152 + 64);
            LDSM4(&bl[0], ka_l + so + nf * 1152);
            LDSM4(&bl[4], ka_l + so + nf * 1152 + 64);
#pragma unroll
            for (int t = 0; t < 4; t++) {
                MMA16816(sacc[nf], qh[t], bh[2 * t], bh[2 * t + 1]);
                MMA16816(sacc[nf], ql[t], bh[2 * t], bh[2 * t + 1]);
                MMA16816(sacc[nf], qh[t], bl[2 * t], bl[2 * t + 1]);
            }
        }

        // ---- online softmax ----
        float tmax0 = -1e30f, tmax1 = -1e30f;
#pragma unroll
        for (int nf = 0; nf < 8; nf++) {
            tmax0 = fmaxf(tmax0, fmaxf(sacc[nf][0], sacc[nf][1]));
            tmax1 = fmaxf(tmax1, fmaxf(sacc[nf][2], sacc[nf][3]));
        }
#pragma unroll
        for (int off = 1; off <= 2; off <<= 1) {
            tmax0 = fmaxf(tmax0, __shfl_xor_sync(0xffffffffu, tmax0, off));
            tmax1 = fmaxf(tmax1, __shfl_xor_sync(0xffffffffu, tmax1, off));
        }
        float m0n = fmaxf(mrow[0], tmax0 * 0.125f);
        float m1n = fmaxf(mrow[1], tmax1 * 0.125f);
        float c0 = __expf(mrow[0] - m0n);
        float c1 = __expf(mrow[1] - m1n);
        mrow[0] = m0n; mrow[1] = m1n;
        lsum[0] *= c0;  lsum[1] *= c1;
#pragma unroll
        for (int nf = 0; nf < 8; nf++) {
            oacc[nf][0] *= c0; oacc[nf][1] *= c0;
            oacc[nf][2] *= c1; oacc[nf][3] *= c1;
        }
        float s0 = 0.f, s1 = 0.f;
#pragma unroll
        for (int nf = 0; nf < 8; nf++) {
            float p0 = __expf(sacc[nf][0] * 0.125f - m0n);
            float p1 = __expf(sacc[nf][1] * 0.125f - m0n);
            float p2 = __expf(sacc[nf][2] * 0.125f - m1n);
            float p3 = __expf(sacc[nf][3] * 0.125f - m1n);
            sacc[nf][0] = p0; sacc[nf][1] = p1;
            sacc[nf][2] = p2; sacc[nf][3] = p3;
            s0 += p0 + p1; s1 += p2 + p3;
        }
#pragma unroll
        for (int off = 1; off <= 2; off <<= 1) {
            s0 += __shfl_xor_sync(0xffffffffu, s0, off);
            s1 += __shfl_xor_sync(0xffffffffu, s1, off);
        }
        lsum[0] += s0; lsum[1] += s1;

        // ---- pack P frags ----
        uint32_t ah[4][4], al[4][4];
#pragma unroll
        for (int t = 0; t < 4; t++) {
            bpack2(sacc[2 * t][0],     sacc[2 * t][1],     ah[t][0], al[t][0]);
            bpack2(sacc[2 * t][2],     sacc[2 * t][3],     ah[t][1], al[t][1]);
            bpack2(sacc[2 * t + 1][0], sacc[2 * t + 1][1], ah[t][2], al[t][2]);
            bpack2(sacc[2 * t + 1][2], sacc[2 * t + 1][3], ah[t][3], al[t][3]);
        }

        // ---- O += P V, 3-pass split ----
#pragma unroll
        for (int nf = 0; nf < 8; nf++) {
            uint32_t vh[8], vl[8];
            LDSM4T(&vh[0], va_h + so + nf * 16);
            LDSM4T(&vh[4], va_h + so + nf * 16 + 32 * 144);
            LDSM4T(&vl[0], va_l + so + nf * 16);
            LDSM4T(&vl[4], va_l + so + nf * 16 + 32 * 144);
#pragma unroll
            for (int t = 0; t < 4; t++) {
                MMA16816(oacc[nf], ah[t], vh[2 * t], vh[2 * t + 1]);
                MMA16816(oacc[nf], al[t], vh[2 * t], vh[2 * t + 1]);
                MMA16816(oacc[nf], ah[t], vl[2 * t], vl[2 * t + 1]);
            }
        }
        __syncthreads();
        if (it + 2 < SQ / 64) issueKV(it + 2);
    }

    // ---- epilogue ----
    const float inv0 = 1.0f / lsum[0];
    const float inv1 = 1.0f / lsum[1];
    const int r  = lane >> 2;
    const int c2 = (lane & 3) * 2;
    const int qrow = q0 + 16 * w + r;
    const size_t ob = ((size_t)(b * SQ + qrow)) * DMODEL + hh * DH + c2;
#pragma unroll
    for (int nf = 0; nf < 8; nf++) {
        uint32_t h01, l01, h23, l23;
        bpack2(oacc[nf][0] * inv0, oacc[nf][1] * inv0, h01, l01);
        bpack2(oacc[nf][2] * inv1, oacc[nf][3] * inv1, h23, l23);
        size_t o = ob + nf * 8;
        *(uint32_t*)(Ohi + o)              = h01;
        *(uint32_t*)(Olo + o)              = l01;
        *(uint32_t*)(Ohi + o + 8 * DMODEL) = h23;
        *(uint32_t*)(Olo + o + 8 * DMODEL) = l23;
    }
}

// ---------------------------------------------------------------------------
extern "C" void kernel_launch(void* const* d_in, const int* in_sizes, int n_in,
                              void* d_out, int out_size)
{
    const float* x  = (const float*)d_in[0];
    const float* wq = (const float*)d_in[2];
    const float* bq = (const float*)d_in[3];
    const float* wk = (const float*)d_in[4];
    const float* bk = (const float*)d_in[5];
    const float* wv = (const float*)d_in[6];
    const float* bv = (const float*)d_in[7];
    const float* wo = (const float*)d_in[8];

    const int B = in_sizes[0] / (SQ * DMODEL);   // 2
    const int M = B * SQ;                        // 4096

    __nv_bfloat16 *qkvhi, *qkvlo, *ahi, *alo, *whi, *wlo;
    float* bias;
    cudaGetSymbolAddress((void**)&qkvhi, g_qkvhi);
    cudaGetSymbolAddress((void**)&qkvlo, g_qkvlo);
    cudaGetSymbolAddress((void**)&ahi,   g_ahi);
    cudaGetSymbolAddress((void**)&alo,   g_alo);
    cudaGetSymbolAddress((void**)&whi,   g_whi);
    cudaGetSymbolAddress((void**)&wlo,   g_wlo);
    cudaGetSymbolAddress((void**)&bias,  g_bias);

    static int attn_smem_set = 0;
    if (!attn_smem_set) {
        cudaFuncSetAttribute(attn_tc_kernel,
                             cudaFuncAttributeMaxDynamicSharedMemorySize,
                             2 * ATTN_STAGE);
        attn_smem_set = 1;
    }

    const int n4 = M * DMODEL / 4;

    split_kernel<<<(n4 + 255) / 256, 256>>>(x, ahi, alo, n4);
    conv_wqkv_kernel<<<(3 * DMODEL * 128) / 256, 256>>>(wq, wk, wv, bq, bk, bv,
                                                        whi, wlo, bias);
    dim3 qkv_grid(3 * DMODEL / 128, M / 128);
    gemm_bf16_split<<<qkv_grid, 256>>>(ahi, alo, whi, wlo, bias,
                                       (float*)nullptr, qkvhi, qkvlo, M);
    dim3 attn_grid(SQ / 64, NH, B);
    attn_tc_kernel<<<attn_grid, 128, 2 * ATTN_STAGE>>>(qkvhi, qkvlo, ahi, alo);
    conv_wo_kernel<<<(DMODEL * 128) / 256, 256>>>(wo, whi, wlo);
    dim3 out_grid(DMODEL / 128, M / 128);
    gemm_bf16_split<<<out_grid, 256>>>(ahi, alo, whi, wlo, (const float*)nullptr,
                                       (float*)d_out, (__nv_bfloat16*)nullptr,
                                       (__nv_bfloat16*)nullptr, M);
}

// round 8
// speedup vs baseline: 1.1863x; 1.1863x over previous
#include <cuda_runtime.h>
#include <cuda_bf16.h>
#include <cstdint>
#include <math.h>

#define SQ     2048
#define DMODEL 1024
#define NH     16
#define DH     64
#define BMAX   2
#define MMAX   (BMAX * SQ)          // 4096

// ---------------- scratch (__device__ globals, allocation-free) -------------
__device__ __nv_bfloat16  g_qkvhi[3 * MMAX * DMODEL];   // q|k|v hi planes
__device__ __nv_bfloat16  g_qkvlo[3 * MMAX * DMODEL];   // q|k|v lo planes
__device__ __nv_bfloat16  g_ahi[MMAX * DMODEL];         // x split / attn-out split
__device__ __nv_bfloat16  g_alo[MMAX * DMODEL];
__device__ __nv_bfloat16  g_whi[3 * DMODEL * DMODEL];   // weights [N][K]
__device__ __nv_bfloat16  g_wlo[3 * DMODEL * DMODEL];
__device__ float          g_bias[3 * DMODEL];

// ---------------------------------------------------------------------------
__device__ __forceinline__ void bsplit(float x, __nv_bfloat16& h, __nv_bfloat16& l)
{
    h = __float2bfloat16_rn(x);
    l = __float2bfloat16_rn(x - __bfloat162float(h));
}

__device__ __forceinline__ void bpack2(float a, float b, uint32_t& hi, uint32_t& lo)
{
    __nv_bfloat16 ha = __float2bfloat16_rn(a), hb = __float2bfloat16_rn(b);
    __nv_bfloat162 H; H.x = ha; H.y = hb;
    __nv_bfloat162 L;
    L.x = __float2bfloat16_rn(a - __bfloat162float(ha));
    L.y = __float2bfloat16_rn(b - __bfloat162float(hb));
    hi = reinterpret_cast<uint32_t&>(H);
    lo = reinterpret_cast<uint32_t&>(L);
}

#define LDSM4(r, a)                                                            \
    asm volatile("ldmatrix.sync.aligned.m8n8.x4.shared.b16 {%0,%1,%2,%3},[%4];"\
                 : "=r"((r)[0]), "=r"((r)[1]), "=r"((r)[2]), "=r"((r)[3])      \
                 : "r"(a))
#define LDSM4T(r, a)                                                           \
    asm volatile("ldmatrix.sync.aligned.m8n8.x4.trans.shared.b16 "             \
                 "{%0,%1,%2,%3},[%4];"                                         \
                 : "=r"((r)[0]), "=r"((r)[1]), "=r"((r)[2]), "=r"((r)[3])      \
                 : "r"(a))
#define MMA16816(d, a, b0, b1)                                                 \
    asm volatile("mma.sync.aligned.m16n8k16.row.col.f32.bf16.bf16.f32 "        \
                 "{%0,%1,%2,%3},{%4,%5,%6,%7},{%8,%9},{%0,%1,%2,%3};"          \
                 : "+f"((d)[0]), "+f"((d)[1]), "+f"((d)[2]), "+f"((d)[3])      \
                 : "r"((a)[0]), "r"((a)[1]), "r"((a)[2]), "r"((a)[3]),         \
                   "r"(b0), "r"(b1))
#define CP16(dst, src)                                                         \
    asm volatile("cp.async.cg.shared.global [%0],[%1],16;"                     \
                 :: "r"(dst), "l"(src))
#define CP_COMMIT  asm volatile("cp.async.commit_group;")
#define CP_WAIT(n) asm volatile("cp.async.wait_group %0;" :: "n"(n))

// ---------------------------------------------------------------------------
__global__ void split_kernel(const float* __restrict__ in,
                             __nv_bfloat16* __restrict__ hi,
                             __nv_bfloat16* __restrict__ lo, int n4)
{
    int i = blockIdx.x * blockDim.x + threadIdx.x;
    if (i >= n4) return;
    float4 v = ((const float4*)in)[i];
    __nv_bfloat16 h0, h1, h2, h3, l0, l1, l2, l3;
    bsplit(v.x, h0, l0); bsplit(v.y, h1, l1);
    bsplit(v.z, h2, l2); bsplit(v.w, h3, l3);
    ushort4 hv = make_ushort4(__bfloat16_as_ushort(h0), __bfloat16_as_ushort(h1),
                              __bfloat16_as_ushort(h2), __bfloat16_as_ushort(h3));
    ushort4 lv = make_ushort4(__bfloat16_as_ushort(l0), __bfloat16_as_ushort(l1),
                              __bfloat16_as_ushort(l2), __bfloat16_as_ushort(l3));
    ((ushort4*)hi)[i] = hv;
    ((ushort4*)lo)[i] = lv;
}

__global__ void conv_wqkv_kernel(const float* __restrict__ wq, const float* __restrict__ wk,
                                 const float* __restrict__ wv, const float* __restrict__ bq,
                                 const float* __restrict__ bk, const float* __restrict__ bv,
                                 __nv_bfloat16* __restrict__ Whi,
                                 __nv_bfloat16* __restrict__ Wlo,
                                 float* __restrict__ gbias)
{
    int gt = blockIdx.x * 256 + threadIdx.x;
    int n  = gt >> 7;
    int d0 = (gt & 127) << 3;
    const float* w  = (n < 1024) ? wq : (n < 2048 ? wk : wv);
    const float* bb = (n < 1024) ? bq : (n < 2048 ? bk : bv);
    int nn = n & 1023, h = nn >> 6, e = nn & 63;
    const float* src = w + h * (DMODEL * DH) + e;

    __nv_bfloat16 hi[8], lo[8];
#pragma unroll
    for (int i = 0; i < 8; i++)
        bsplit(src[(size_t)(d0 + i) * DH], hi[i], lo[i]);

    size_t o = (size_t)n * DMODEL + d0;
    *(uint4*)(Whi + o) = *(const uint4*)hi;
    *(uint4*)(Wlo + o) = *(const uint4*)lo;
    if (d0 == 0) gbias[n] = bb[nn];
}

__global__ void conv_wo_kernel(const float* __restrict__ wo,
                               __nv_bfloat16* __restrict__ Whi,
                               __nv_bfloat16* __restrict__ Wlo)
{
    int gt = blockIdx.x * 256 + threadIdx.x;
    int n  = gt >> 7;
    int d0 = (gt & 127) << 3;
    __nv_bfloat16 hi[8], lo[8];
#pragma unroll
    for (int i = 0; i < 8; i++)
        bsplit(wo[(size_t)(d0 + i) * DMODEL + n], hi[i], lo[i]);
    size_t o = (size_t)n * DMODEL + d0;
    *(uint4*)(Whi + o) = *(const uint4*)hi;
    *(uint4*)(Wlo + o) = *(const uint4*)lo;
}

// ---------------------------------------------------------------------------
// Tensor-core GEMM, bf16 x3 split, cp.async 2-stage pipeline. (unchanged R6)
// ---------------------------------------------------------------------------
__global__ __launch_bounds__(256)
void gemm_bf16_split(const __nv_bfloat16* __restrict__ Ahi,
                     const __nv_bfloat16* __restrict__ Alo,
                     const __nv_bfloat16* __restrict__ Whi,
                     const __nv_bfloat16* __restrict__ Wlo,
                     const float* __restrict__ bias,
                     float* __restrict__ C,
                     __nv_bfloat16* __restrict__ Chi,
                     __nv_bfloat16* __restrict__ Clo, int M)
{
    __shared__ __align__(16) __nv_bfloat16 As[2][128][40];
    __shared__ __align__(16) __nv_bfloat16 Bs[2][128][40];
    const uint32_t STG = 128 * 40 * 2;

    const int tid  = threadIdx.x;
    const int lane = tid & 31;
    const int wid  = tid >> 5;
    const int wm   = (wid & 3) * 32;
    const int wn   = (wid >> 2) * 64;
    const int m0   = blockIdx.y * 128;
    const int n0   = blockIdx.x * 128;

    const int lrow = tid >> 2;
    const int lcol = (tid & 3) * 8;

    float acc[2][8][4];
#pragma unroll
    for (int i = 0; i < 2; i++)
#pragma unroll
        for (int j = 0; j < 8; j++)
#pragma unroll
            for (int c = 0; c < 4; c++) acc[i][j][c] = 0.f;

    uint32_t a_addr[2], b_addr[4];
#pragma unroll
    for (int mi = 0; mi < 2; mi++)
        a_addr[mi] = (uint32_t)__cvta_generic_to_shared(
            &As[0][wm + mi * 16 + (lane & 15)][(lane >> 4) * 8]);
#pragma unroll
    for (int np = 0; np < 4; np++) {
        int g = lane >> 3, r = lane & 7;
        b_addr[np] = (uint32_t)__cvta_generic_to_shared(
            &Bs[0][wn + np * 16 + (g >> 1) * 8 + r][(g & 1) * 8]);
    }
    const uint32_t as_dst = (uint32_t)__cvta_generic_to_shared(&As[0][lrow][lcol]);
    const uint32_t bs_dst = (uint32_t)__cvta_generic_to_shared(&Bs[0][lrow][lcol]);
    const uint32_t row64  = 64 * 40 * 2;

    auto issue = [&](int blk) {
        int p  = blk >> 5;
        int k0 = (blk & 31) << 5;
        const __nv_bfloat16* Ap = (p == 1) ? Alo : Ahi;
        const __nv_bfloat16* Wp = (p == 2) ? Wlo : Whi;
        const __nv_bfloat16* ag = Ap + (size_t)(m0 + lrow) * DMODEL + lcol + k0;
        const __nv_bfloat16* bg = Wp + (size_t)(n0 + lrow) * DMODEL + lcol + k0;
        uint32_t so = (blk & 1) * STG;
        CP16(as_dst + so,         ag);
        CP16(as_dst + so + row64, ag + (size_t)64 * DMODEL);
        CP16(bs_dst + so,         bg);
        CP16(bs_dst + so + row64, bg + (size_t)64 * DMODEL);
        CP_COMMIT;
    };

    issue(0);
    issue(1);

    for (int blk = 0; blk < 96; blk++) {
        if (blk == 95) { CP_WAIT(0); } else { CP_WAIT(1); }
        __syncthreads();

        const uint32_t so = (blk & 1) * STG;
#pragma unroll
        for (int ks = 0; ks < 32; ks += 16) {
            uint32_t af[2][4];
#pragma unroll
            for (int mi = 0; mi < 2; mi++)
                LDSM4(af[mi], a_addr[mi] + so + ks * 2);
#pragma unroll
            for (int np = 0; np < 4; np++) {
                uint32_t bf[4];
                LDSM4(bf, b_addr[np] + so + ks * 2);
#pragma unroll
                for (int mi = 0; mi < 2; mi++) {
                    MMA16816(acc[mi][np * 2],     af[mi], bf[0], bf[1]);
                    MMA16816(acc[mi][np * 2 + 1], af[mi], bf[2], bf[3]);
                }
            }
        }
        __syncthreads();
        if (blk + 2 < 96) issue(blk + 2);
    }

    const size_t plane = (size_t)M * DMODEL;
#pragma unroll
    for (int mi = 0; mi < 2; mi++) {
        int row = m0 + wm + mi * 16 + (lane >> 2);
#pragma unroll
        for (int ni = 0; ni < 8; ni++) {
            int col = n0 + wn + ni * 8 + (lane & 3) * 2;
            float b0 = bias ? bias[col]     : 0.f;
            float b1 = bias ? bias[col + 1] : 0.f;
            float v0 = acc[mi][ni][0] + b0, v1 = acc[mi][ni][1] + b1;
            float v2 = acc[mi][ni][2] + b0, v3 = acc[mi][ni][3] + b1;
            size_t o = (size_t)(col >> 10) * plane
                     + (size_t)row * DMODEL + (col & 1023);
            if (Chi) {
                uint32_t h01, l01, h23, l23;
                bpack2(v0, v1, h01, l01);
                bpack2(v2, v3, h23, l23);
                *(uint32_t*)(Chi + o)               = h01;
                *(uint32_t*)(Clo + o)               = l01;
                *(uint32_t*)(Chi + o + 8 * DMODEL)  = h23;
                *(uint32_t*)(Clo + o + 8 * DMODEL)  = l23;
            } else {
                *(float2*)(C + o)              = make_float2(v0, v1);
                *(float2*)(C + o + 8 * DMODEL) = make_float2(v2, v3);
            }
        }
    }
}

// ---------------------------------------------------------------------------
// Tensor-core flash attention. LDG+STS tile loads (L1-cached), 4 CTAs/SM:
// __launch_bounds__(128,4) + Q-lo frags in smem (not registers).
// smem: Khs,Kls,Vhs,Vls,Qls = 5 x 64x72 bf16 = 46 KB static.
// ---------------------------------------------------------------------------
__global__ __launch_bounds__(128, 4)
void attn_tc_kernel(const __nv_bfloat16* __restrict__ Phi,
                    const __nv_bfloat16* __restrict__ Plo,
                    __nv_bfloat16* __restrict__ Ohi,
                    __nv_bfloat16* __restrict__ Olo)
{
    __shared__ __align__(16) __nv_bfloat16 Khs[64][72];
    __shared__ __align__(16) __nv_bfloat16 Kls[64][72];
    __shared__ __align__(16) __nv_bfloat16 Vhs[64][72];
    __shared__ __align__(16) __nv_bfloat16 Vls[64][72];
    __shared__ __align__(16) __nv_bfloat16 Qls[64][72];

    const int tid  = threadIdx.x;
    const int lane = tid & 31;
    const int w    = tid >> 5;
    const int hh   = blockIdx.y;
    const int b    = blockIdx.z;
    const int q0   = blockIdx.x * 64;
    const float SC = 0.18033688f;     // 0.125 * log2(e)

    const size_t plane = (size_t)gridDim.z * SQ * DMODEL;
    const __nv_bfloat16* Qh = Phi;
    const __nv_bfloat16* Ql = Plo;
    const __nv_bfloat16* Kh = Phi + plane;
    const __nv_bfloat16* Kl = Plo + plane;
    const __nv_bfloat16* Vh = Phi + 2 * plane;
    const __nv_bfloat16* Vl = Plo + 2 * plane;

    const int ldr = tid >> 1;
    const int ldc = (tid & 1) * 32;
    const size_t gb = ((size_t)b * SQ) * DMODEL + hh * DH;

    // ---- stage Q: hi via Khs (transient), lo into persistent Qls ----
    {
        const __nv_bfloat16* sh = Qh + gb + (size_t)(q0 + ldr) * DMODEL + ldc;
        const __nv_bfloat16* sl = Ql + gb + (size_t)(q0 + ldr) * DMODEL + ldc;
#pragma unroll
        for (int i = 0; i < 4; i++) {
            *(uint4*)&Khs[ldr][ldc + 8 * i] = *(const uint4*)(sh + 8 * i);
            *(uint4*)&Qls[ldr][ldc + 8 * i] = *(const uint4*)(sl + 8 * i);
        }
    }
    __syncthreads();
    uint32_t qh[4][4];
    const uint32_t qla = (uint32_t)__cvta_generic_to_shared(
        &Qls[16 * w + (lane & 15)][(lane >> 4) * 8]);
    {
        uint32_t qa = (uint32_t)__cvta_generic_to_shared(
            &Khs[16 * w + (lane & 15)][(lane >> 4) * 8]);
#pragma unroll
        for (int t = 0; t < 4; t++) LDSM4(qh[t], qa + t * 32);
    }

    const uint32_t ka_h = (uint32_t)__cvta_generic_to_shared(
        &Khs[lane & 7][(lane >> 3) * 8]);
    const uint32_t ka_l = (uint32_t)__cvta_generic_to_shared(
        &Kls[lane & 7][(lane >> 3) * 8]);
    const uint32_t va_h = (uint32_t)__cvta_generic_to_shared(&Vhs[lane][0]);
    const uint32_t va_l = (uint32_t)__cvta_generic_to_shared(&Vls[lane][0]);

    float oacc[8][4];
#pragma unroll
    for (int i = 0; i < 8; i++)
#pragma unroll
        for (int c = 0; c < 4; c++) oacc[i][c] = 0.f;
    float mrow[2] = {-1e30f, -1e30f};     // in log2 domain
    float lsum[2] = {0.f, 0.f};

    for (int kt = 0; kt < SQ; kt += 64) {
        __syncthreads();
        {
            const size_t g = gb + (size_t)(kt + ldr) * DMODEL + ldc;
#pragma unroll
            for (int i = 0; i < 4; i++) {
                *(uint4*)&Khs[ldr][ldc + 8 * i] = *(const uint4*)(Kh + g + 8 * i);
                *(uint4*)&Kls[ldr][ldc + 8 * i] = *(const uint4*)(Kl + g + 8 * i);
                *(uint4*)&Vhs[ldr][ldc + 8 * i] = *(const uint4*)(Vh + g + 8 * i);
                *(uint4*)&Vls[ldr][ldc + 8 * i] = *(const uint4*)(Vl + g + 8 * i);
            }
        }
        __syncthreads();

        // Q-lo frags from smem (keeps register count under the 128 cap)
        uint32_t qlf[4][4];
#pragma unroll
        for (int t = 0; t < 4; t++) LDSM4(qlf[t], qla + t * 32);

        // ---- S = Q K^T, 3-pass split ----
        float sacc[8][4];
#pragma unroll
        for (int nf = 0; nf < 8; nf++) {
#pragma unroll
            for (int c = 0; c < 4; c++) sacc[nf][c] = 0.f;
            uint32_t bh[8], bl[8];
            LDSM4(&bh[0], ka_h + nf * 1152);
            LDSM4(&bh[4], ka_h + nf * 1152 + 64);
            LDSM4(&bl[0], ka_l + nf * 1152);
            LDSM4(&bl[4], ka_l + nf * 1152 + 64);
#pragma unroll
            for (int t = 0; t < 4; t++) {
                MMA16816(sacc[nf], qh[t],  bh[2 * t], bh[2 * t + 1]);
                MMA16816(sacc[nf], qlf[t], bh[2 * t], bh[2 * t + 1]);
                MMA16816(sacc[nf], qh[t],  bl[2 * t], bl[2 * t + 1]);
            }
        }

        // ---- online softmax (base-2 domain) ----
#pragma unroll
        for (int nf = 0; nf < 8; nf++) {
#pragma unroll
            for (int c = 0; c < 4; c++) sacc[nf][c] *= SC;
        }
        float tmax0 = -1e30f, tmax1 = -1e30f;
#pragma unroll
        for (int nf = 0; nf < 8; nf++) {
            tmax0 = fmaxf(tmax0, fmaxf(sacc[nf][0], sacc[nf][1]));
            tmax1 = fmaxf(tmax1, fmaxf(sacc[nf][2], sacc[nf][3]));
        }
#pragma unroll
        for (int off = 1; off <= 2; off <<= 1) {
            tmax0 = fmaxf(tmax0, __shfl_xor_sync(0xffffffffu, tmax0, off));
            tmax1 = fmaxf(tmax1, __shfl_xor_sync(0xffffffffu, tmax1, off));
        }
        float m0n = fmaxf(mrow[0], tmax0);
        float m1n = fmaxf(mrow[1], tmax1);
        float c0 = exp2f(mrow[0] - m0n);
        float c1 = exp2f(mrow[1] - m1n);
        mrow[0] = m0n; mrow[1] = m1n;
        lsum[0] *= c0;  lsum[1] *= c1;
#pragma unroll
        for (int nf = 0; nf < 8; nf++) {
            oacc[nf][0] *= c0; oacc[nf][1] *= c0;
            oacc[nf][2] *= c1; oacc[nf][3] *= c1;
        }
        float s0 = 0.f, s1 = 0.f;
#pragma unroll
        for (int nf = 0; nf < 8; nf++) {
            float p0 = exp2f(sacc[nf][0] - m0n);
            float p1 = exp2f(sacc[nf][1] - m0n);
            float p2 = exp2f(sacc[nf][2] - m1n);
            float p3 = exp2f(sacc[nf][3] - m1n);
            sacc[nf][0] = p0; sacc[nf][1] = p1;
            sacc[nf][2] = p2; sacc[nf][3] = p3;
            s0 += p0 + p1; s1 += p2 + p3;
        }
#pragma unroll
        for (int off = 1; off <= 2; off <<= 1) {
            s0 += __shfl_xor_sync(0xffffffffu, s0, off);
            s1 += __shfl_xor_sync(0xffffffffu, s1, off);
        }
        lsum[0] += s0; lsum[1] += s1;

        // ---- pack P frags ----
        uint32_t ah[4][4], al[4][4];
#pragma unroll
        for (int t = 0; t < 4; t++) {
            bpack2(sacc[2 * t][0],     sacc[2 * t][1],     ah[t][0], al[t][0]);
            bpack2(sacc[2 * t][2],     sacc[2 * t][3],     ah[t][1], al[t][1]);
            bpack2(sacc[2 * t + 1][0], sacc[2 * t + 1][1], ah[t][2], al[t][2]);
            bpack2(sacc[2 * t + 1][2], sacc[2 * t + 1][3], ah[t][3], al[t][3]);
        }

        // ---- O += P V, 3-pass split ----
#pragma unroll
        for (int nf = 0; nf < 8; nf++) {
            uint32_t vh[8], vl[8];
            LDSM4T(&vh[0], va_h + nf * 16);
            LDSM4T(&vh[4], va_h + nf * 16 + 32 * 144);
            LDSM4T(&vl[0], va_l + nf * 16);
            LDSM4T(&vl[4], va_l + nf * 16 + 32 * 144);
#pragma unroll
            for (int t = 0; t < 4; t++) {
                MMA16816(oacc[nf], ah[t], vh[2 * t], vh[2 * t + 1]);
                MMA16816(oacc[nf], al[t], vh[2 * t], vh[2 * t + 1]);
                MMA16816(oacc[nf], ah[t], vl[2 * t], vl[2 * t + 1]);
            }
        }
    }

    // ---- epilogue ----
    const float inv0 = 1.0f / lsum[0];
    const float inv1 = 1.0f / lsum[1];
    const int r  = lane >> 2;
    const int c2 = (lane & 3) * 2;
    const int qrow = q0 + 16 * w + r;
    const size_t ob = ((size_t)(b * SQ + qrow)) * DMODEL + hh * DH + c2;
#pragma unroll
    for (int nf = 0; nf < 8; nf++) {
        uint32_t h01, l01, h23, l23;
        bpack2(oacc[nf][0] * inv0, oacc[nf][1] * inv0, h01, l01);
        bpack2(oacc[nf][2] * inv1, oacc[nf][3] * inv1, h23, l23);
        size_t o = ob + nf * 8;
        *(uint32_t*)(Ohi + o)              = h01;
        *(uint32_t*)(Olo + o)              = l01;
        *(uint32_t*)(Ohi + o + 8 * DMODEL) = h23;
        *(uint32_t*)(Olo + o + 8 * DMODEL) = l23;
    }
}

// ---------------------------------------------------------------------------
extern "C" void kernel_launch(void* const* d_in, const int* in_sizes, int n_in,
                              void* d_out, int out_size)
{
    const float* x  = (const float*)d_in[0];
    const float* wq = (const float*)d_in[2];
    const float* bq = (const float*)d_in[3];
    const float* wk = (const float*)d_in[4];
    const float* bk = (const float*)d_in[5];
    const float* wv = (const float*)d_in[6];
    const float* bv = (const float*)d_in[7];
    const float* wo = (const float*)d_in[8];

    const int B = in_sizes[0] / (SQ * DMODEL);   // 2
    const int M = B * SQ;                        // 4096

    __nv_bfloat16 *qkvhi, *qkvlo, *ahi, *alo, *whi, *wlo;
    float* bias;
    cudaGetSymbolAddress((void**)&qkvhi, g_qkvhi);
    cudaGetSymbolAddress((void**)&qkvlo, g_qkvlo);
    cudaGetSymbolAddress((void**)&ahi,   g_ahi);
    cudaGetSymbolAddress((void**)&alo,   g_alo);
    cudaGetSymbolAddress((void**)&whi,   g_whi);
    cudaGetSymbolAddress((void**)&wlo,   g_wlo);
    cudaGetSymbolAddress((void**)&bias,  g_bias);

    const int n4 = M * DMODEL / 4;

    split_kernel<<<(n4 + 255) / 256, 256>>>(x, ahi, alo, n4);
    conv_wqkv_kernel<<<(3 * DMODEL * 128) / 256, 256>>>(wq, wk, wv, bq, bk, bv,
                                                        whi, wlo, bias);
    dim3 qkv_grid(3 * DMODEL / 128, M / 128);
    gemm_bf16_split<<<qkv_grid, 256>>>(ahi, alo, whi, wlo, bias,
                                       (float*)nullptr, qkvhi, qkvlo, M);
    dim3 attn_grid(SQ / 64, NH, B);
    attn_tc_kernel<<<attn_grid, 128>>>(qkvhi, qkvlo, ahi, alo);
    conv_wo_kernel<<<(DMODEL * 128) / 256, 256>>>(wo, whi, wlo);
    dim3 out_grid(DMODEL / 128, M / 128);
    gemm_bf16_split<<<out_grid, 256>>>(ahi, alo, whi, wlo, (const float*)nullptr,
                                       (float*)d_out, (__nv_bfloat16*)nullptr,
                                       (__nv_bfloat16*)nullptr, M);
}

// round 9
// speedup vs baseline: 1.2604x; 1.0625x over previous
#include <cuda_runtime.h>
#include <cuda_bf16.h>
#include <cstdint>
#include <math.h>

#define SQ     2048
#define DMODEL 1024
#define NH     16
#define DH     64
#define BMAX   2
#define MMAX   (BMAX * SQ)          // 4096

// ---------------- scratch (__device__ globals, allocation-free) -------------
__device__ __nv_bfloat16  g_qkvhi[3 * MMAX * DMODEL];   // q|k|v hi planes
__device__ __nv_bfloat16  g_qkvlo[3 * MMAX * DMODEL];   // q|k|v lo planes
__device__ __nv_bfloat16  g_ahi[MMAX * DMODEL];         // x split / attn-out split
__device__ __nv_bfloat16  g_alo[MMAX * DMODEL];
__device__ __nv_bfloat16  g_whi[3 * DMODEL * DMODEL];   // weights [N][K]
__device__ __nv_bfloat16  g_wlo[3 * DMODEL * DMODEL];
__device__ float          g_bias[3 * DMODEL];

// ---------------------------------------------------------------------------
__device__ __forceinline__ void bsplit(float x, __nv_bfloat16& h, __nv_bfloat16& l)
{
    h = __float2bfloat16_rn(x);
    l = __float2bfloat16_rn(x - __bfloat162float(h));
}

__device__ __forceinline__ void bpack2(float a, float b, uint32_t& hi, uint32_t& lo)
{
    __nv_bfloat16 ha = __float2bfloat16_rn(a), hb = __float2bfloat16_rn(b);
    __nv_bfloat162 H; H.x = ha; H.y = hb;
    __nv_bfloat162 L;
    L.x = __float2bfloat16_rn(a - __bfloat162float(ha));
    L.y = __float2bfloat16_rn(b - __bfloat162float(hb));
    hi = reinterpret_cast<uint32_t&>(H);
    lo = reinterpret_cast<uint32_t&>(L);
}

#define LDSM4(r, a)                                                            \
    asm volatile("ldmatrix.sync.aligned.m8n8.x4.shared.b16 {%0,%1,%2,%3},[%4];"\
                 : "=r"((r)[0]), "=r"((r)[1]), "=r"((r)[2]), "=r"((r)[3])      \
                 : "r"(a))
#define LDSM4T(r, a)                                                           \
    asm volatile("ldmatrix.sync.aligned.m8n8.x4.trans.shared.b16 "             \
                 "{%0,%1,%2,%3},[%4];"                                         \
                 : "=r"((r)[0]), "=r"((r)[1]), "=r"((r)[2]), "=r"((r)[3])      \
                 : "r"(a))
#define MMA16816(d, a, b0, b1)                                                 \
    asm volatile("mma.sync.aligned.m16n8k16.row.col.f32.bf16.bf16.f32 "        \
                 "{%0,%1,%2,%3},{%4,%5,%6,%7},{%8,%9},{%0,%1,%2,%3};"          \
                 : "+f"((d)[0]), "+f"((d)[1]), "+f"((d)[2]), "+f"((d)[3])      \
                 : "r"((a)[0]), "r"((a)[1]), "r"((a)[2]), "r"((a)[3]),         \
                   "r"(b0), "r"(b1))
#define CP16(dst, src)                                                         \
    asm volatile("cp.async.cg.shared.global [%0],[%1],16;"                     \
                 :: "r"(dst), "l"(src))
#define CP_COMMIT  asm volatile("cp.async.commit_group;")
#define CP_WAIT(n) asm volatile("cp.async.wait_group %0;" :: "n"(n))

// ---------------------------------------------------------------------------
__global__ void split_kernel(const float* __restrict__ in,
                             __nv_bfloat16* __restrict__ hi,
                             __nv_bfloat16* __restrict__ lo, int n4)
{
    int i = blockIdx.x * blockDim.x + threadIdx.x;
    if (i >= n4) return;
    float4 v = ((const float4*)in)[i];
    __nv_bfloat16 h0, h1, h2, h3, l0, l1, l2, l3;
    bsplit(v.x, h0, l0); bsplit(v.y, h1, l1);
    bsplit(v.z, h2, l2); bsplit(v.w, h3, l3);
    ushort4 hv = make_ushort4(__bfloat16_as_ushort(h0), __bfloat16_as_ushort(h1),
                              __bfloat16_as_ushort(h2), __bfloat16_as_ushort(h3));
    ushort4 lv = make_ushort4(__bfloat16_as_ushort(l0), __bfloat16_as_ushort(l1),
                              __bfloat16_as_ushort(l2), __bfloat16_as_ushort(l3));
    ((ushort4*)hi)[i] = hv;
    ((ushort4*)lo)[i] = lv;
}

__global__ void conv_wqkv_kernel(const float* __restrict__ wq, const float* __restrict__ wk,
                                 const float* __restrict__ wv, const float* __restrict__ bq,
                                 const float* __restrict__ bk, const float* __restrict__ bv,
                                 __nv_bfloat16* __restrict__ Whi,
                                 __nv_bfloat16* __restrict__ Wlo,
                                 float* __restrict__ gbias)
{
    int gt = blockIdx.x * 256 + threadIdx.x;
    int n  = gt >> 7;
    int d0 = (gt & 127) << 3;
    const float* w  = (n < 1024) ? wq : (n < 2048 ? wk : wv);
    const float* bb = (n < 1024) ? bq : (n < 2048 ? bk : bv);
    int nn = n & 1023, h = nn >> 6, e = nn & 63;
    const float* src = w + h * (DMODEL * DH) + e;

    __nv_bfloat16 hi[8], lo[8];
#pragma unroll
    for (int i = 0; i < 8; i++)
        bsplit(src[(size_t)(d0 + i) * DH], hi[i], lo[i]);

    size_t o = (size_t)n * DMODEL + d0;
    *(uint4*)(Whi + o) = *(const uint4*)hi;
    *(uint4*)(Wlo + o) = *(const uint4*)lo;
    if (d0 == 0) gbias[n] = bb[nn];
}

__global__ void conv_wo_kernel(const float* __restrict__ wo,
                               __nv_bfloat16* __restrict__ Whi,
                               __nv_bfloat16* __restrict__ Wlo)
{
    int gt = blockIdx.x * 256 + threadIdx.x;
    int n  = gt >> 7;
    int d0 = (gt & 127) << 3;
    __nv_bfloat16 hi[8], lo[8];
#pragma unroll
    for (int i = 0; i < 8; i++)
        bsplit(wo[(size_t)(d0 + i) * DMODEL + n], hi[i], lo[i]);
    size_t o = (size_t)n * DMODEL + d0;
    *(uint4*)(Whi + o) = *(const uint4*)hi;
    *(uint4*)(Wlo + o) = *(const uint4*)lo;
}

// ---------------------------------------------------------------------------
// Tensor-core GEMM, bf16 x3 split, cp.async 2-stage pipeline. (unchanged)
// ---------------------------------------------------------------------------
__global__ __launch_bounds__(256)
void gemm_bf16_split(const __nv_bfloat16* __restrict__ Ahi,
                     const __nv_bfloat16* __restrict__ Alo,
                     const __nv_bfloat16* __restrict__ Whi,
                     const __nv_bfloat16* __restrict__ Wlo,
                     const float* __restrict__ bias,
                     float* __restrict__ C,
                     __nv_bfloat16* __restrict__ Chi,
                     __nv_bfloat16* __restrict__ Clo, int M)
{
    __shared__ __align__(16) __nv_bfloat16 As[2][128][40];
    __shared__ __align__(16) __nv_bfloat16 Bs[2][128][40];
    const uint32_t STG = 128 * 40 * 2;

    const int tid  = threadIdx.x;
    const int lane = tid & 31;
    const int wid  = tid >> 5;
    const int wm   = (wid & 3) * 32;
    const int wn   = (wid >> 2) * 64;
    const int m0   = blockIdx.y * 128;
    const int n0   = blockIdx.x * 128;

    const int lrow = tid >> 2;
    const int lcol = (tid & 3) * 8;

    float acc[2][8][4];
#pragma unroll
    for (int i = 0; i < 2; i++)
#pragma unroll
        for (int j = 0; j < 8; j++)
#pragma unroll
            for (int c = 0; c < 4; c++) acc[i][j][c] = 0.f;

    uint32_t a_addr[2], b_addr[4];
#pragma unroll
    for (int mi = 0; mi < 2; mi++)
        a_addr[mi] = (uint32_t)__cvta_generic_to_shared(
            &As[0][wm + mi * 16 + (lane & 15)][(lane >> 4) * 8]);
#pragma unroll
    for (int np = 0; np < 4; np++) {
        int g = lane >> 3, r = lane & 7;
        b_addr[np] = (uint32_t)__cvta_generic_to_shared(
            &Bs[0][wn + np * 16 + (g >> 1) * 8 + r][(g & 1) * 8]);
    }
    const uint32_t as_dst = (uint32_t)__cvta_generic_to_shared(&As[0][lrow][lcol]);
    const uint32_t bs_dst = (uint32_t)__cvta_generic_to_shared(&Bs[0][lrow][lcol]);
    const uint32_t row64  = 64 * 40 * 2;

    auto issue = [&](int blk) {
        int p  = blk >> 5;
        int k0 = (blk & 31) << 5;
        const __nv_bfloat16* Ap = (p == 1) ? Alo : Ahi;
        const __nv_bfloat16* Wp = (p == 2) ? Wlo : Whi;
        const __nv_bfloat16* ag = Ap + (size_t)(m0 + lrow) * DMODEL + lcol + k0;
        const __nv_bfloat16* bg = Wp + (size_t)(n0 + lrow) * DMODEL + lcol + k0;
        uint32_t so = (blk & 1) * STG;
        CP16(as_dst + so,         ag);
        CP16(as_dst + so + row64, ag + (size_t)64 * DMODEL);
        CP16(bs_dst + so,         bg);
        CP16(bs_dst + so + row64, bg + (size_t)64 * DMODEL);
        CP_COMMIT;
    };

    issue(0);
    issue(1);

    for (int blk = 0; blk < 96; blk++) {
        if (blk == 95) { CP_WAIT(0); } else { CP_WAIT(1); }
        __syncthreads();

        const uint32_t so = (blk & 1) * STG;
#pragma unroll
        for (int ks = 0; ks < 32; ks += 16) {
            uint32_t af[2][4];
#pragma unroll
            for (int mi = 0; mi < 2; mi++)
                LDSM4(af[mi], a_addr[mi] + so + ks * 2);
#pragma unroll
            for (int np = 0; np < 4; np++) {
                uint32_t bf[4];
                LDSM4(bf, b_addr[np] + so + ks * 2);
#pragma unroll
                for (int mi = 0; mi < 2; mi++) {
                    MMA16816(acc[mi][np * 2],     af[mi], bf[0], bf[1]);
                    MMA16816(acc[mi][np * 2 + 1], af[mi], bf[2], bf[3]);
                }
            }
        }
        __syncthreads();
        if (blk + 2 < 96) issue(blk + 2);
    }

    const size_t plane = (size_t)M * DMODEL;
#pragma unroll
    for (int mi = 0; mi < 2; mi++) {
        int row = m0 + wm + mi * 16 + (lane >> 2);
#pragma unroll
        for (int ni = 0; ni < 8; ni++) {
            int col = n0 + wn + ni * 8 + (lane & 3) * 2;
            float b0 = bias ? bias[col]     : 0.f;
            float b1 = bias ? bias[col + 1] : 0.f;
            float v0 = acc[mi][ni][0] + b0, v1 = acc[mi][ni][1] + b1;
            float v2 = acc[mi][ni][2] + b0, v3 = acc[mi][ni][3] + b1;
            size_t o = (size_t)(col >> 10) * plane
                     + (size_t)row * DMODEL + (col & 1023);
            if (Chi) {
                uint32_t h01, l01, h23, l23;
                bpack2(v0, v1, h01, l01);
                bpack2(v2, v3, h23, l23);
                *(uint32_t*)(Chi + o)               = h01;
                *(uint32_t*)(Clo + o)               = l01;
                *(uint32_t*)(Chi + o + 8 * DMODEL)  = h23;
                *(uint32_t*)(Clo + o + 8 * DMODEL)  = l23;
            } else {
                *(float2*)(C + o)              = make_float2(v0, v1);
                *(float2*)(C + o + 8 * DMODEL) = make_float2(v2, v3);
            }
        }
    }
}

// ---------------------------------------------------------------------------
// Tensor-core flash attention, 128-query CTAs (2 m-tiles/warp).
// Each K/V ldmatrix now feeds 2x the MMA work (MMA:LDSM 2.8 -> 4.0).
// Dynamic smem 72 KB: Khs Kls Vhs Vls (64x72 each) + Qhs Qls (128x72 each).
// S computed in 2 sweeps sharing one 32-reg Q fragment buffer to stay
// under the 256-reg (128,2) cap.
// ---------------------------------------------------------------------------
#define A_OFF_KH 0
#define A_OFF_KL 9216
#define A_OFF_VH 18432
#define A_OFF_VL 27648
#define A_OFF_QH 36864
#define A_OFF_QL 55296
#define A_SMEM   73728

extern __shared__ __align__(16) char dynsm[];

__global__ __launch_bounds__(128, 2)
void attn_tc_kernel(const __nv_bfloat16* __restrict__ Phi,
                    const __nv_bfloat16* __restrict__ Plo,
                    __nv_bfloat16* __restrict__ Ohi,
                    __nv_bfloat16* __restrict__ Olo)
{
    const int tid  = threadIdx.x;
    const int lane = tid & 31;
    const int w    = tid >> 5;
    const int hh   = blockIdx.y;
    const int b    = blockIdx.z;
    const int q0   = blockIdx.x * 128;
    const float SC = 0.18033688f;     // 0.125 * log2(e)

    const size_t plane = (size_t)gridDim.z * SQ * DMODEL;
    const __nv_bfloat16* Qh = Phi;
    const __nv_bfloat16* Ql = Plo;
    const __nv_bfloat16* Kh = Phi + plane;
    const __nv_bfloat16* Kl = Plo + plane;
    const __nv_bfloat16* Vh = Phi + 2 * plane;
    const __nv_bfloat16* Vl = Plo + 2 * plane;

    const int ldr = tid >> 1;           // 0..63
    const int ldc = (tid & 1) * 32;     // 0/32
    const size_t gb = ((size_t)b * SQ) * DMODEL + hh * DH;

    const uint32_t sb = (uint32_t)__cvta_generic_to_shared(dynsm);

    // ---- stage Q (128 rows, hi+lo) into persistent smem ----
#pragma unroll
    for (int half = 0; half < 2; half++) {
        const int row = half * 64 + ldr;
        const __nv_bfloat16* sh = Qh + gb + (size_t)(q0 + row) * DMODEL + ldc;
        const __nv_bfloat16* sl = Ql + gb + (size_t)(q0 + row) * DMODEL + ldc;
        __nv_bfloat16* dh = (__nv_bfloat16*)(dynsm + A_OFF_QH) + row * 72 + ldc;
        __nv_bfloat16* dl = (__nv_bfloat16*)(dynsm + A_OFF_QL) + row * 72 + ldc;
#pragma unroll
        for (int i = 0; i < 4; i++) {
            *(uint4*)(dh + 8 * i) = *(const uint4*)(sh + 8 * i);
            *(uint4*)(dl + 8 * i) = *(const uint4*)(sl + 8 * i);
        }
    }

    // Q fragment ldmatrix addresses per m-tile
    uint32_t qh_addr[2], ql_addr[2];
#pragma unroll
    for (int mi = 0; mi < 2; mi++) {
        uint32_t roff = (uint32_t)((32 * w + 16 * mi + (lane & 15)) * 72
                                   + (lane >> 4) * 8) * 2;
        qh_addr[mi] = sb + A_OFF_QH + roff;
        ql_addr[mi] = sb + A_OFF_QL + roff;
    }

    const uint32_t ka_h = sb + A_OFF_KH + (uint32_t)((lane & 7) * 72 + (lane >> 3) * 8) * 2;
    const uint32_t ka_l = sb + A_OFF_KL + (uint32_t)((lane & 7) * 72 + (lane >> 3) * 8) * 2;
    const uint32_t va_h = sb + A_OFF_VH + (uint32_t)(lane * 72) * 2;
    const uint32_t va_l = sb + A_OFF_VL + (uint32_t)(lane * 72) * 2;

    float oacc[2][8][4];
#pragma unroll
    for (int mi = 0; mi < 2; mi++)
#pragma unroll
        for (int i = 0; i < 8; i++)
#pragma unroll
            for (int c = 0; c < 4; c++) oacc[mi][i][c] = 0.f;
    float mrow[2][2] = {{-1e30f, -1e30f}, {-1e30f, -1e30f}};
    float lsum[2][2] = {{0.f, 0.f}, {0.f, 0.f}};

    for (int kt = 0; kt < SQ; kt += 64) {
        __syncthreads();
        {
            const size_t g = gb + (size_t)(kt + ldr) * DMODEL + ldc;
            __nv_bfloat16* dkh = (__nv_bfloat16*)(dynsm + A_OFF_KH) + ldr * 72 + ldc;
            __nv_bfloat16* dkl = (__nv_bfloat16*)(dynsm + A_OFF_KL) + ldr * 72 + ldc;
            __nv_bfloat16* dvh = (__nv_bfloat16*)(dynsm + A_OFF_VH) + ldr * 72 + ldc;
            __nv_bfloat16* dvl = (__nv_bfloat16*)(dynsm + A_OFF_VL) + ldr * 72 + ldc;
#pragma unroll
            for (int i = 0; i < 4; i++) {
                *(uint4*)(dkh + 8 * i) = *(const uint4*)(Kh + g + 8 * i);
                *(uint4*)(dkl + 8 * i) = *(const uint4*)(Kl + g + 8 * i);
                *(uint4*)(dvh + 8 * i) = *(const uint4*)(Vh + g + 8 * i);
                *(uint4*)(dvl + 8 * i) = *(const uint4*)(Vl + g + 8 * i);
            }
        }
        __syncthreads();

        float sacc[2][8][4];
#pragma unroll
        for (int mi = 0; mi < 2; mi++)
#pragma unroll
            for (int nf = 0; nf < 8; nf++)
#pragma unroll
                for (int c = 0; c < 4; c++) sacc[mi][nf][c] = 0.f;

        // ---- sweep A: qh * (Kh + Kl) ----
        uint32_t qf[2][4][4];
#pragma unroll
        for (int mi = 0; mi < 2; mi++)
#pragma unroll
            for (int t = 0; t < 4; t++) LDSM4(qf[mi][t], qh_addr[mi] + t * 32);
#pragma unroll
        for (int nf = 0; nf < 8; nf++) {
            uint32_t bh[8], bl[8];
            LDSM4(&bh[0], ka_h + nf * 1152);
            LDSM4(&bh[4], ka_h + nf * 1152 + 64);
            LDSM4(&bl[0], ka_l + nf * 1152);
            LDSM4(&bl[4], ka_l + nf * 1152 + 64);
#pragma unroll
            for (int mi = 0; mi < 2; mi++)
#pragma unroll
                for (int t = 0; t < 4; t++) {
                    MMA16816(sacc[mi][nf], qf[mi][t], bh[2 * t], bh[2 * t + 1]);
                    MMA16816(sacc[mi][nf], qf[mi][t], bl[2 * t], bl[2 * t + 1]);
                }
        }
        // ---- sweep B: ql * Kh ----
#pragma unroll
        for (int mi = 0; mi < 2; mi++)
#pragma unroll
            for (int t = 0; t < 4; t++) LDSM4(qf[mi][t], ql_addr[mi] + t * 32);
#pragma unroll
        for (int nf = 0; nf < 8; nf++) {
            uint32_t bh[8];
            LDSM4(&bh[0], ka_h + nf * 1152);
            LDSM4(&bh[4], ka_h + nf * 1152 + 64);
#pragma unroll
            for (int mi = 0; mi < 2; mi++)
#pragma unroll
                for (int t = 0; t < 4; t++)
                    MMA16816(sacc[mi][nf], qf[mi][t], bh[2 * t], bh[2 * t + 1]);
        }

        // ---- online softmax (base-2 domain), per m-tile ----
        uint32_t ah[2][4][4], al[2][4][4];
#pragma unroll
        for (int mi = 0; mi < 2; mi++) {
#pragma unroll
            for (int nf = 0; nf < 8; nf++)
#pragma unroll
                for (int c = 0; c < 4; c++) sacc[mi][nf][c] *= SC;
            float tmax0 = -1e30f, tmax1 = -1e30f;
#pragma unroll
            for (int nf = 0; nf < 8; nf++) {
                tmax0 = fmaxf(tmax0, fmaxf(sacc[mi][nf][0], sacc[mi][nf][1]));
                tmax1 = fmaxf(tmax1, fmaxf(sacc[mi][nf][2], sacc[mi][nf][3]));
            }
#pragma unroll
            for (int off = 1; off <= 2; off <<= 1) {
                tmax0 = fmaxf(tmax0, __shfl_xor_sync(0xffffffffu, tmax0, off));
                tmax1 = fmaxf(tmax1, __shfl_xor_sync(0xffffffffu, tmax1, off));
            }
            float m0n = fmaxf(mrow[mi][0], tmax0);
            float m1n = fmaxf(mrow[mi][1], tmax1);
            float c0 = exp2f(mrow[mi][0] - m0n);
            float c1 = exp2f(mrow[mi][1] - m1n);
            mrow[mi][0] = m0n; mrow[mi][1] = m1n;
            lsum[mi][0] *= c0;  lsum[mi][1] *= c1;
#pragma unroll
            for (int nf = 0; nf < 8; nf++) {
                oacc[mi][nf][0] *= c0; oacc[mi][nf][1] *= c0;
                oacc[mi][nf][2] *= c1; oacc[mi][nf][3] *= c1;
            }
            float s0 = 0.f, s1 = 0.f;
#pragma unroll
            for (int nf = 0; nf < 8; nf++) {
                float p0 = exp2f(sacc[mi][nf][0] - m0n);
                float p1 = exp2f(sacc[mi][nf][1] - m0n);
                float p2 = exp2f(sacc[mi][nf][2] - m1n);
                float p3 = exp2f(sacc[mi][nf][3] - m1n);
                sacc[mi][nf][0] = p0; sacc[mi][nf][1] = p1;
                sacc[mi][nf][2] = p2; sacc[mi][nf][3] = p3;
                s0 += p0 + p1; s1 += p2 + p3;
            }
#pragma unroll
            for (int off = 1; off <= 2; off <<= 1) {
                s0 += __shfl_xor_sync(0xffffffffu, s0, off);
                s1 += __shfl_xor_sync(0xffffffffu, s1, off);
            }
            lsum[mi][0] += s0; lsum[mi][1] += s1;

            // pack P frags for this m-tile
#pragma unroll
            for (int t = 0; t < 4; t++) {
                bpack2(sacc[mi][2 * t][0],     sacc[mi][2 * t][1],     ah[mi][t][0], al[mi][t][0]);
                bpack2(sacc[mi][2 * t][2],     sacc[mi][2 * t][3],     ah[mi][t][1], al[mi][t][1]);
                bpack2(sacc[mi][2 * t + 1][0], sacc[mi][2 * t + 1][1], ah[mi][t][2], al[mi][t][2]);
                bpack2(sacc[mi][2 * t + 1][2], sacc[mi][2 * t + 1][3], ah[mi][t][3], al[mi][t][3]);
            }
        }

        // ---- O += P V, 3-pass split ----
#pragma unroll
        for (int nf = 0; nf < 8; nf++) {
            uint32_t vh[8], vl[8];
            LDSM4T(&vh[0], va_h + nf * 16);
            LDSM4T(&vh[4], va_h + nf * 16 + 32 * 144);
            LDSM4T(&vl[0], va_l + nf * 16);
            LDSM4T(&vl[4], va_l + nf * 16 + 32 * 144);
#pragma unroll
            for (int mi = 0; mi < 2; mi++)
#pragma unroll
                for (int t = 0; t < 4; t++) {
                    MMA16816(oacc[mi][nf], ah[mi][t], vh[2 * t], vh[2 * t + 1]);
                    MMA16816(oacc[mi][nf], al[mi][t], vh[2 * t], vh[2 * t + 1]);
                    MMA16816(oacc[mi][nf], ah[mi][t], vl[2 * t], vl[2 * t + 1]);
                }
        }
    }

    // ---- epilogue ----
    const int r  = lane >> 2;
    const int c2 = (lane & 3) * 2;
#pragma unroll
    for (int mi = 0; mi < 2; mi++) {
        const float inv0 = 1.0f / lsum[mi][0];
        const float inv1 = 1.0f / lsum[mi][1];
        const int qrow = q0 + 32 * w + 16 * mi + r;
        const size_t ob = ((size_t)(b * SQ + qrow)) * DMODEL + hh * DH + c2;
#pragma unroll
        for (int nf = 0; nf < 8; nf++) {
            uint32_t h01, l01, h23, l23;
            bpack2(oacc[mi][nf][0] * inv0, oacc[mi][nf][1] * inv0, h01, l01);
            bpack2(oacc[mi][nf][2] * inv1, oacc[mi][nf][3] * inv1, h23, l23);
            size_t o = ob + nf * 8;
            *(uint32_t*)(Ohi + o)              = h01;
            *(uint32_t*)(Olo + o)              = l01;
            *(uint32_t*)(Ohi + o + 8 * DMODEL) = h23;
            *(uint32_t*)(Olo + o + 8 * DMODEL) = l23;
        }
    }
}

// ---------------------------------------------------------------------------
extern "C" void kernel_launch(void* const* d_in, const int* in_sizes, int n_in,
                              void* d_out, int out_size)
{
    const float* x  = (const float*)d_in[0];
    const float* wq = (const float*)d_in[2];
    const float* bq = (const float*)d_in[3];
    const float* wk = (const float*)d_in[4];
    const float* bk = (const float*)d_in[5];
    const float* wv = (const float*)d_in[6];
    const float* bv = (const float*)d_in[7];
    const float* wo = (const float*)d_in[8];

    const int B = in_sizes[0] / (SQ * DMODEL);   // 2
    const int M = B * SQ;                        // 4096

    __nv_bfloat16 *qkvhi, *qkvlo, *ahi, *alo, *whi, *wlo;
    float* bias;
    cudaGetSymbolAddress((void**)&qkvhi, g_qkvhi);
    cudaGetSymbolAddress((void**)&qkvlo, g_qkvlo);
    cudaGetSymbolAddress((void**)&ahi,   g_ahi);
    cudaGetSymbolAddress((void**)&alo,   g_alo);
    cudaGetSymbolAddress((void**)&whi,   g_whi);
    cudaGetSymbolAddress((void**)&wlo,   g_wlo);
    cudaGetSymbolAddress((void**)&bias,  g_bias);

    static int attn_smem_set = 0;
    if (!attn_smem_set) {
        cudaFuncSetAttribute(attn_tc_kernel,
                             cudaFuncAttributeMaxDynamicSharedMemorySize,
                             A_SMEM);
        attn_smem_set = 1;
    }

    const int n4 = M * DMODEL / 4;

    split_kernel<<<(n4 + 255) / 256, 256>>>(x, ahi, alo, n4);
    conv_wqkv_kernel<<<(3 * DMODEL * 128) / 256, 256>>>(wq, wk, wv, bq, bk, bv,
                                                        whi, wlo, bias);
    dim3 qkv_grid(3 * DMODEL / 128, M / 128);
    gemm_bf16_split<<<qkv_grid, 256>>>(ahi, alo, whi, wlo, bias,
                                       (float*)nullptr, qkvhi, qkvlo, M);
    dim3 attn_grid(SQ / 128, NH, B);
    attn_tc_kernel<<<attn_grid, 128, A_SMEM>>>(qkvhi, qkvlo, ahi, alo);
    conv_wo_kernel<<<(DMODEL * 128) / 256, 256>>>(wo, whi, wlo);
    dim3 out_grid(DMODEL / 128, M / 128);
    gemm_bf16_split<<<out_grid, 256>>>(ahi, alo, whi, wlo, (const float*)nullptr,
                                       (float*)d_out, (__nv_bfloat16*)nullptr,
                                       (__nv_bfloat16*)nullptr, M);
}

// round 10
// speedup vs baseline: 1.3225x; 1.0493x over previous
#include <cuda_runtime.h>
#include <cuda_bf16.h>
#include <cstdint>
#include <math.h>

#define SQ     2048
#define DMODEL 1024
#define NH     16
#define DH     64
#define BMAX   2
#define MMAX   (BMAX * SQ)          // 4096

// ---------------- scratch (__device__ globals, allocation-free) -------------
__device__ __nv_bfloat16  g_qkvhi[3 * MMAX * DMODEL];   // q|k|v hi planes
__device__ __nv_bfloat16  g_qkvlo[3 * MMAX * DMODEL];   // q|k|v lo planes
__device__ __nv_bfloat16  g_ahi[MMAX * DMODEL];         // x split / attn-out split
__device__ __nv_bfloat16  g_alo[MMAX * DMODEL];
__device__ __nv_bfloat16  g_whi[3 * DMODEL * DMODEL];   // weights [N][K]
__device__ __nv_bfloat16  g_wlo[3 * DMODEL * DMODEL];
__device__ float          g_bias[3 * DMODEL];

// ---------------------------------------------------------------------------
__device__ __forceinline__ void bsplit(float x, __nv_bfloat16& h, __nv_bfloat16& l)
{
    h = __float2bfloat16_rn(x);
    l = __float2bfloat16_rn(x - __bfloat162float(h));
}

__device__ __forceinline__ void bpack2(float a, float b, uint32_t& hi, uint32_t& lo)
{
    __nv_bfloat16 ha = __float2bfloat16_rn(a), hb = __float2bfloat16_rn(b);
    __nv_bfloat162 H; H.x = ha; H.y = hb;
    __nv_bfloat162 L;
    L.x = __float2bfloat16_rn(a - __bfloat162float(ha));
    L.y = __float2bfloat16_rn(b - __bfloat162float(hb));
    hi = reinterpret_cast<uint32_t&>(H);
    lo = reinterpret_cast<uint32_t&>(L);
}

#define LDSM4(r, a)                                                            \
    asm volatile("ldmatrix.sync.aligned.m8n8.x4.shared.b16 {%0,%1,%2,%3},[%4];"\
                 : "=r"((r)[0]), "=r"((r)[1]), "=r"((r)[2]), "=r"((r)[3])      \
                 : "r"(a))
#define LDSM4T(r, a)                                                           \
    asm volatile("ldmatrix.sync.aligned.m8n8.x4.trans.shared.b16 "             \
                 "{%0,%1,%2,%3},[%4];"                                         \
                 : "=r"((r)[0]), "=r"((r)[1]), "=r"((r)[2]), "=r"((r)[3])      \
                 : "r"(a))
#define MMA16816(d, a, b0, b1)                                                 \
    asm volatile("mma.sync.aligned.m16n8k16.row.col.f32.bf16.bf16.f32 "        \
                 "{%0,%1,%2,%3},{%4,%5,%6,%7},{%8,%9},{%0,%1,%2,%3};"          \
                 : "+f"((d)[0]), "+f"((d)[1]), "+f"((d)[2]), "+f"((d)[3])      \
                 : "r"((a)[0]), "r"((a)[1]), "r"((a)[2]), "r"((a)[3]),         \
                   "r"(b0), "r"(b1))
// L1-caching async copy (R6 lesson: .cg bypasses L1 and regressed)
#define CP16A(dst, src)                                                        \
    asm volatile("cp.async.ca.shared.global [%0],[%1],16;"                     \
                 :: "r"(dst), "l"(src))
#define CP_COMMIT  asm volatile("cp.async.commit_group;")
#define CP_WAIT(n) asm volatile("cp.async.wait_group %0;" :: "n"(n))

extern __shared__ __align__(16) char dynsm[];

// ---------------------------------------------------------------------------
__global__ void split_kernel(const float* __restrict__ in,
                             __nv_bfloat16* __restrict__ hi,
                             __nv_bfloat16* __restrict__ lo, int n4)
{
    int i = blockIdx.x * blockDim.x + threadIdx.x;
    if (i >= n4) return;
    float4 v = ((const float4*)in)[i];
    __nv_bfloat16 h0, h1, h2, h3, l0, l1, l2, l3;
    bsplit(v.x, h0, l0); bsplit(v.y, h1, l1);
    bsplit(v.z, h2, l2); bsplit(v.w, h3, l3);
    ushort4 hv = make_ushort4(__bfloat16_as_ushort(h0), __bfloat16_as_ushort(h1),
                              __bfloat16_as_ushort(h2), __bfloat16_as_ushort(h3));
    ushort4 lv = make_ushort4(__bfloat16_as_ushort(l0), __bfloat16_as_ushort(l1),
                              __bfloat16_as_ushort(l2), __bfloat16_as_ushort(l3));
    ((ushort4*)hi)[i] = hv;
    ((ushort4*)lo)[i] = lv;
}

__global__ void conv_wqkv_kernel(const float* __restrict__ wq, const float* __restrict__ wk,
                                 const float* __restrict__ wv, const float* __restrict__ bq,
                                 const float* __restrict__ bk, const float* __restrict__ bv,
                                 __nv_bfloat16* __restrict__ Whi,
                                 __nv_bfloat16* __restrict__ Wlo,
                                 float* __restrict__ gbias)
{
    int gt = blockIdx.x * 256 + threadIdx.x;
    int n  = gt >> 7;
    int d0 = (gt & 127) << 3;
    const float* w  = (n < 1024) ? wq : (n < 2048 ? wk : wv);
    const float* bb = (n < 1024) ? bq : (n < 2048 ? bk : bv);
    int nn = n & 1023, h = nn >> 6, e = nn & 63;
    const float* src = w + h * (DMODEL * DH) + e;

    __nv_bfloat16 hi[8], lo[8];
#pragma unroll
    for (int i = 0; i < 8; i++)
        bsplit(src[(size_t)(d0 + i) * DH], hi[i], lo[i]);

    size_t o = (size_t)n * DMODEL + d0;
    *(uint4*)(Whi + o) = *(const uint4*)hi;
    *(uint4*)(Wlo + o) = *(const uint4*)lo;
    if (d0 == 0) gbias[n] = bb[nn];
}

__global__ void conv_wo_kernel(const float* __restrict__ wo,
                               __nv_bfloat16* __restrict__ Whi,
                               __nv_bfloat16* __restrict__ Wlo)
{
    int gt = blockIdx.x * 256 + threadIdx.x;
    int n  = gt >> 7;
    int d0 = (gt & 127) << 3;
    __nv_bfloat16 hi[8], lo[8];
#pragma unroll
    for (int i = 0; i < 8; i++)
        bsplit(wo[(size_t)(d0 + i) * DMODEL + n], hi[i], lo[i]);
    size_t o = (size_t)n * DMODEL + d0;
    *(uint4*)(Whi + o) = *(const uint4*)hi;
    *(uint4*)(Wlo + o) = *(const uint4*)lo;
}

// ---------------------------------------------------------------------------
// Fused-pass tensor-core GEMM: per k-block load Ahi/Alo/Whi/Wlo tiles ONCE,
// issue all three split products (hh, lh, hl). 2-stage cp.async.ca pipeline.
// Dynamic smem: 2 stages x 4 planes x (128x40 bf16) = 80 KB.
// ---------------------------------------------------------------------------
#define G_AH 0
#define G_AL 10240
#define G_BH 20480
#define G_BL 30720
#define G_STG 40960
#define G_SMEM 81920

__global__ __launch_bounds__(256)
void gemm_bf16_split(const __nv_bfloat16* __restrict__ Ahi,
                     const __nv_bfloat16* __restrict__ Alo,
                     const __nv_bfloat16* __restrict__ Whi,
                     const __nv_bfloat16* __restrict__ Wlo,
                     const float* __restrict__ bias,
                     float* __restrict__ C,
                     __nv_bfloat16* __restrict__ Chi,
                     __nv_bfloat16* __restrict__ Clo, int M)
{
    const int tid  = threadIdx.x;
    const int lane = tid & 31;
    const int wid  = tid >> 5;
    const int wm   = (wid & 3) * 32;
    const int wn   = (wid >> 2) * 64;
    const int m0   = blockIdx.y * 128;
    const int n0   = blockIdx.x * 128;

    const int lrow = tid >> 2;          // 0..63
    const int lcol = (tid & 3) * 8;     // 0..24

    float acc[2][8][4];
#pragma unroll
    for (int i = 0; i < 2; i++)
#pragma unroll
        for (int j = 0; j < 8; j++)
#pragma unroll
            for (int c = 0; c < 4; c++) acc[i][j][c] = 0.f;

    const uint32_t sb = (uint32_t)__cvta_generic_to_shared(dynsm);
    uint32_t a_off[2], b_off[4];
#pragma unroll
    for (int mi = 0; mi < 2; mi++)
        a_off[mi] = (uint32_t)((wm + mi * 16 + (lane & 15)) * 40
                               + (lane >> 4) * 8) * 2;
#pragma unroll
    for (int np = 0; np < 4; np++) {
        int g = lane >> 3, r = lane & 7;
        b_off[np] = (uint32_t)((wn + np * 16 + (g >> 1) * 8 + r) * 40
                               + (g & 1) * 8) * 2;
    }
    const uint32_t ld_off = (uint32_t)(lrow * 40 + lcol) * 2;
    const uint32_t row64  = 64 * 40 * 2;

    auto issue = [&](int blk) {
        const int k0 = blk << 5;
        const __nv_bfloat16* agh = Ahi + (size_t)(m0 + lrow) * DMODEL + lcol + k0;
        const __nv_bfloat16* agl = Alo + (size_t)(m0 + lrow) * DMODEL + lcol + k0;
        const __nv_bfloat16* bgh = Whi + (size_t)(n0 + lrow) * DMODEL + lcol + k0;
        const __nv_bfloat16* bgl = Wlo + (size_t)(n0 + lrow) * DMODEL + lcol + k0;
        const uint32_t s = sb + (blk & 1) * G_STG + ld_off;
        CP16A(s + G_AH,         agh);
        CP16A(s + G_AH + row64, agh + (size_t)64 * DMODEL);
        CP16A(s + G_AL,         agl);
        CP16A(s + G_AL + row64, agl + (size_t)64 * DMODEL);
        CP16A(s + G_BH,         bgh);
        CP16A(s + G_BH + row64, bgh + (size_t)64 * DMODEL);
        CP16A(s + G_BL,         bgl);
        CP16A(s + G_BL + row64, bgl + (size_t)64 * DMODEL);
        CP_COMMIT;
    };

    issue(0);
    issue(1);

    for (int blk = 0; blk < 32; blk++) {
        if (blk == 31) { CP_WAIT(0); } else { CP_WAIT(1); }
        __syncthreads();
        const uint32_t so = sb + (blk & 1) * G_STG;

#pragma unroll
        for (int ks = 0; ks < 32; ks += 16) {
            uint32_t afh[2][4], afl[2][4];
#pragma unroll
            for (int mi = 0; mi < 2; mi++) {
                LDSM4(afh[mi], so + G_AH + a_off[mi] + ks * 2);
                LDSM4(afl[mi], so + G_AL + a_off[mi] + ks * 2);
            }
#pragma unroll
            for (int np = 0; np < 4; np++) {
                uint32_t bfh[4], bfl[4];
                LDSM4(bfh, so + G_BH + b_off[np] + ks * 2);
                LDSM4(bfl, so + G_BL + b_off[np] + ks * 2);
#pragma unroll
                for (int mi = 0; mi < 2; mi++) {
                    MMA16816(acc[mi][np * 2],     afh[mi], bfh[0], bfh[1]);
                    MMA16816(acc[mi][np * 2 + 1], afh[mi], bfh[2], bfh[3]);
                    MMA16816(acc[mi][np * 2],     afl[mi], bfh[0], bfh[1]);
                    MMA16816(acc[mi][np * 2 + 1], afl[mi], bfh[2], bfh[3]);
                    MMA16816(acc[mi][np * 2],     afh[mi], bfl[0], bfl[1]);
                    MMA16816(acc[mi][np * 2 + 1], afh[mi], bfl[2], bfl[3]);
                }
            }
        }
        __syncthreads();
        if (blk + 2 < 32) issue(blk + 2);
    }

    const size_t plane = (size_t)M * DMODEL;
#pragma unroll
    for (int mi = 0; mi < 2; mi++) {
        int row = m0 + wm + mi * 16 + (lane >> 2);
#pragma unroll
        for (int ni = 0; ni < 8; ni++) {
            int col = n0 + wn + ni * 8 + (lane & 3) * 2;
            float b0 = bias ? bias[col]     : 0.f;
            float b1 = bias ? bias[col + 1] : 0.f;
            float v0 = acc[mi][ni][0] + b0, v1 = acc[mi][ni][1] + b1;
            float v2 = acc[mi][ni][2] + b0, v3 = acc[mi][ni][3] + b1;
            size_t o = (size_t)(col >> 10) * plane
                     + (size_t)row * DMODEL + (col & 1023);
            if (Chi) {
                uint32_t h01, l01, h23, l23;
                bpack2(v0, v1, h01, l01);
                bpack2(v2, v3, h23, l23);
                *(uint32_t*)(Chi + o)               = h01;
                *(uint32_t*)(Clo + o)               = l01;
                *(uint32_t*)(Chi + o + 8 * DMODEL)  = h23;
                *(uint32_t*)(Clo + o + 8 * DMODEL)  = l23;
            } else {
                *(float2*)(C + o)              = make_float2(v0, v1);
                *(float2*)(C + o + 8 * DMODEL) = make_float2(v2, v3);
            }
        }
    }
}

// ---------------------------------------------------------------------------
// Tensor-core flash attention, 128-query CTAs, 2-stage cp.async.ca K/V
// pipeline. Dynamic smem 108 KB: 2 x (Kh,Kl,Vh,Vl 64x72) + Qh,Ql 128x72.
// ---------------------------------------------------------------------------
#define T_KH 0
#define T_KL 9216
#define T_VH 18432
#define T_VL 27648
#define T_STG 36864
#define T_QH 73728
#define T_QL 92160
#define T_SMEM 110592

__global__ __launch_bounds__(128, 2)
void attn_tc_kernel(const __nv_bfloat16* __restrict__ Phi,
                    const __nv_bfloat16* __restrict__ Plo,
                    __nv_bfloat16* __restrict__ Ohi,
                    __nv_bfloat16* __restrict__ Olo)
{
    const int tid  = threadIdx.x;
    const int lane = tid & 31;
    const int w    = tid >> 5;
    const int hh   = blockIdx.y;
    const int b    = blockIdx.z;
    const int q0   = blockIdx.x * 128;
    const float SC = 0.18033688f;     // 0.125 * log2(e)

    const size_t plane = (size_t)gridDim.z * SQ * DMODEL;
    const __nv_bfloat16* Qh = Phi;
    const __nv_bfloat16* Ql = Plo;
    const __nv_bfloat16* Kh = Phi + plane;
    const __nv_bfloat16* Kl = Plo + plane;
    const __nv_bfloat16* Vh = Phi + 2 * plane;
    const __nv_bfloat16* Vl = Plo + 2 * plane;

    const int ldr = tid >> 1;           // 0..63
    const int ldc = (tid & 1) * 32;     // 0/32
    const size_t gb = ((size_t)b * SQ) * DMODEL + hh * DH;

    const uint32_t sb = (uint32_t)__cvta_generic_to_shared(dynsm);

    // ---- stage Q (128 rows, hi+lo) into persistent smem ----
#pragma unroll
    for (int half = 0; half < 2; half++) {
        const int row = half * 64 + ldr;
        const __nv_bfloat16* sh = Qh + gb + (size_t)(q0 + row) * DMODEL + ldc;
        const __nv_bfloat16* sl = Ql + gb + (size_t)(q0 + row) * DMODEL + ldc;
        __nv_bfloat16* dh = (__nv_bfloat16*)(dynsm + T_QH) + row * 72 + ldc;
        __nv_bfloat16* dl = (__nv_bfloat16*)(dynsm + T_QL) + row * 72 + ldc;
#pragma unroll
        for (int i = 0; i < 4; i++) {
            *(uint4*)(dh + 8 * i) = *(const uint4*)(sh + 8 * i);
            *(uint4*)(dl + 8 * i) = *(const uint4*)(sl + 8 * i);
        }
    }

    // Q fragment ldmatrix addresses per m-tile
    uint32_t qh_addr[2], ql_addr[2];
#pragma unroll
    for (int mi = 0; mi < 2; mi++) {
        uint32_t roff = (uint32_t)((32 * w + 16 * mi + (lane & 15)) * 72
                                   + (lane >> 4) * 8) * 2;
        qh_addr[mi] = sb + T_QH + roff;
        ql_addr[mi] = sb + T_QL + roff;
    }

    const uint32_t kbase = sb + (uint32_t)((lane & 7) * 72 + (lane >> 3) * 8) * 2;
    const uint32_t vbase = sb + (uint32_t)(lane * 72) * 2;
    const uint32_t ld_off = (uint32_t)(ldr * 72 + ldc) * 2;

    auto issueKV = [&](int it) {
        const int kt = it * 64;
        const size_t g = gb + (size_t)(kt + ldr) * DMODEL + ldc;
        const uint32_t s = sb + (it & 1) * T_STG + ld_off;
#pragma unroll
        for (int i = 0; i < 4; i++) {
            CP16A(s + T_KH + 16 * i, Kh + g + 8 * i);
            CP16A(s + T_KL + 16 * i, Kl + g + 8 * i);
            CP16A(s + T_VH + 16 * i, Vh + g + 8 * i);
            CP16A(s + T_VL + 16 * i, Vl + g + 8 * i);
        }
        CP_COMMIT;
    };

    float oacc[2][8][4];
#pragma unroll
    for (int mi = 0; mi < 2; mi++)
#pragma unroll
        for (int i = 0; i < 8; i++)
#pragma unroll
            for (int c = 0; c < 4; c++) oacc[mi][i][c] = 0.f;
    float mrow[2][2] = {{-1e30f, -1e30f}, {-1e30f, -1e30f}};
    float lsum[2][2] = {{0.f, 0.f}, {0.f, 0.f}};

    issueKV(0);
    issueKV(1);

    for (int it = 0; it < SQ / 64; it++) {
        if (it == SQ / 64 - 1) { CP_WAIT(0); } else { CP_WAIT(1); }
        __syncthreads();
        const uint32_t so = (it & 1) * T_STG;
        const uint32_t ka_h = kbase + T_KH + so;
        const uint32_t ka_l = kbase + T_KL + so;
        const uint32_t va_h = vbase + T_VH + so;
        const uint32_t va_l = vbase + T_VL + so;

        float sacc[2][8][4];
#pragma unroll
        for (int mi = 0; mi < 2; mi++)
#pragma unroll
            for (int nf = 0; nf < 8; nf++)
#pragma unroll
                for (int c = 0; c < 4; c++) sacc[mi][nf][c] = 0.f;

        // ---- sweep A: qh * (Kh + Kl) ----
        uint32_t qf[2][4][4];
#pragma unroll
        for (int mi = 0; mi < 2; mi++)
#pragma unroll
            for (int t = 0; t < 4; t++) LDSM4(qf[mi][t], qh_addr[mi] + t * 32);
#pragma unroll
        for (int nf = 0; nf < 8; nf++) {
            uint32_t bh[8], bl[8];
            LDSM4(&bh[0], ka_h + nf * 1152);
            LDSM4(&bh[4], ka_h + nf * 1152 + 64);
            LDSM4(&bl[0], ka_l + nf * 1152);
            LDSM4(&bl[4], ka_l + nf * 1152 + 64);
#pragma unroll
            for (int mi = 0; mi < 2; mi++)
#pragma unroll
                for (int t = 0; t < 4; t++) {
                    MMA16816(sacc[mi][nf], qf[mi][t], bh[2 * t], bh[2 * t + 1]);
                    MMA16816(sacc[mi][nf], qf[mi][t], bl[2 * t], bl[2 * t + 1]);
                }
        }
        // ---- sweep B: ql * Kh ----
#pragma unroll
        for (int mi = 0; mi < 2; mi++)
#pragma unroll
            for (int t = 0; t < 4; t++) LDSM4(qf[mi][t], ql_addr[mi] + t * 32);
#pragma unroll
        for (int nf = 0; nf < 8; nf++) {
            uint32_t bh[8];
            LDSM4(&bh[0], ka_h + nf * 1152);
            LDSM4(&bh[4], ka_h + nf * 1152 + 64);
#pragma unroll
            for (int mi = 0; mi < 2; mi++)
#pragma unroll
                for (int t = 0; t < 4; t++)
                    MMA16816(sacc[mi][nf], qf[mi][t], bh[2 * t], bh[2 * t + 1]);
        }

        // ---- online softmax (base-2 domain), per m-tile ----
        uint32_t ah[2][4][4], al[2][4][4];
#pragma unroll
        for (int mi = 0; mi < 2; mi++) {
#pragma unroll
            for (int nf = 0; nf < 8; nf++)
#pragma unroll
                for (int c = 0; c < 4; c++) sacc[mi][nf][c] *= SC;
            float tmax0 = -1e30f, tmax1 = -1e30f;
#pragma unroll
            for (int nf = 0; nf < 8; nf++) {
                tmax0 = fmaxf(tmax0, fmaxf(sacc[mi][nf][0], sacc[mi][nf][1]));
                tmax1 = fmaxf(tmax1, fmaxf(sacc[mi][nf][2], sacc[mi][nf][3]));
            }
#pragma unroll
            for (int off = 1; off <= 2; off <<= 1) {
                tmax0 = fmaxf(tmax0, __shfl_xor_sync(0xffffffffu, tmax0, off));
                tmax1 = fmaxf(tmax1, __shfl_xor_sync(0xffffffffu, tmax1, off));
            }
            float m0n = fmaxf(mrow[mi][0], tmax0);
            float m1n = fmaxf(mrow[mi][1], tmax1);
            float c0 = exp2f(mrow[mi][0] - m0n);
            float c1 = exp2f(mrow[mi][1] - m1n);
            mrow[mi][0] = m0n; mrow[mi][1] = m1n;
            lsum[mi][0] *= c0;  lsum[mi][1] *= c1;
#pragma unroll
            for (int nf = 0; nf < 8; nf++) {
                oacc[mi][nf][0] *= c0; oacc[mi][nf][1] *= c0;
                oacc[mi][nf][2] *= c1; oacc[mi][nf][3] *= c1;
            }
            float s0 = 0.f, s1 = 0.f;
#pragma unroll
            for (int nf = 0; nf < 8; nf++) {
                float p0 = exp2f(sacc[mi][nf][0] - m0n);
                float p1 = exp2f(sacc[mi][nf][1] - m0n);
                float p2 = exp2f(sacc[mi][nf][2] - m1n);
                float p3 = exp2f(sacc[mi][nf][3] - m1n);
                sacc[mi][nf][0] = p0; sacc[mi][nf][1] = p1;
                sacc[mi][nf][2] = p2; sacc[mi][nf][3] = p3;
                s0 += p0 + p1; s1 += p2 + p3;
            }
#pragma unroll
            for (int off = 1; off <= 2; off <<= 1) {
                s0 += __shfl_xor_sync(0xffffffffu, s0, off);
                s1 += __shfl_xor_sync(0xffffffffu, s1, off);
            }
            lsum[mi][0] += s0; lsum[mi][1] += s1;

#pragma unroll
            for (int t = 0; t < 4; t++) {
                bpack2(sacc[mi][2 * t][0],     sacc[mi][2 * t][1],     ah[mi][t][0], al[mi][t][0]);
                bpack2(sacc[mi][2 * t][2],     sacc[mi][2 * t][3],     ah[mi][t][1], al[mi][t][1]);
                bpack2(sacc[mi][2 * t + 1][0], sacc[mi][2 * t + 1][1], ah[mi][t][2], al[mi][t][2]);
                bpack2(sacc[mi][2 * t + 1][2], sacc[mi][2 * t + 1][3], ah[mi][t][3], al[mi][t][3]);
            }
        }

        // ---- O += P V, 3-pass split ----
#pragma unroll
        for (int nf = 0; nf < 8; nf++) {
            uint32_t vh[8], vl[8];
            LDSM4T(&vh[0], va_h + nf * 16);
            LDSM4T(&vh[4], va_h + nf * 16 + 32 * 144);
            LDSM4T(&vl[0], va_l + nf * 16);
            LDSM4T(&vl[4], va_l + nf * 16 + 32 * 144);
#pragma unroll
            for (int mi = 0; mi < 2; mi++)
#pragma unroll
                for (int t = 0; t < 4; t++) {
                    MMA16816(oacc[mi][nf], ah[mi][t], vh[2 * t], vh[2 * t + 1]);
                    MMA16816(oacc[mi][nf], al[mi][t], vh[2 * t], vh[2 * t + 1]);
                    MMA16816(oacc[mi][nf], ah[mi][t], vl[2 * t], vl[2 * t + 1]);
                }
        }
        __syncthreads();
        if (it + 2 < SQ / 64) issueKV(it + 2);
    }

    // ---- epilogue ----
    const int r  = lane >> 2;
    const int c2 = (lane & 3) * 2;
#pragma unroll
    for (int mi = 0; mi < 2; mi++) {
        const float inv0 = 1.0f / lsum[mi][0];
        const float inv1 = 1.0f / lsum[mi][1];
        const int qrow = q0 + 32 * w + 16 * mi + r;
        const size_t ob = ((size_t)(b * SQ + qrow)) * DMODEL + hh * DH + c2;
#pragma unroll
        for (int nf = 0; nf < 8; nf++) {
            uint32_t h01, l01, h23, l23;
            bpack2(oacc[mi][nf][0] * inv0, oacc[mi][nf][1] * inv0, h01, l01);
            bpack2(oacc[mi][nf][2] * inv1, oacc[mi][nf][3] * inv1, h23, l23);
            size_t o = ob + nf * 8;
            *(uint32_t*)(Ohi + o)              = h01;
            *(uint32_t*)(Olo + o)              = l01;
            *(uint32_t*)(Ohi + o + 8 * DMODEL) = h23;
            *(uint32_t*)(Olo + o + 8 * DMODEL) = l23;
        }
    }
}

// ---------------------------------------------------------------------------
extern "C" void kernel_launch(void* const* d_in, const int* in_sizes, int n_in,
                              void* d_out, int out_size)
{
    const float* x  = (const float*)d_in[0];
    const float* wq = (const float*)d_in[2];
    const float* bq = (const float*)d_in[3];
    const float* wk = (const float*)d_in[4];
    const float* bk = (const float*)d_in[5];
    const float* wv = (const float*)d_in[6];
    const float* bv = (const float*)d_in[7];
    const float* wo = (const float*)d_in[8];

    const int B = in_sizes[0] / (SQ * DMODEL);   // 2
    const int M = B * SQ;                        // 4096

    __nv_bfloat16 *qkvhi, *qkvlo, *ahi, *alo, *whi, *wlo;
    float* bias;
    cudaGetSymbolAddress((void**)&qkvhi, g_qkvhi);
    cudaGetSymbolAddress((void**)&qkvlo, g_qkvlo);
    cudaGetSymbolAddress((void**)&ahi,   g_ahi);
    cudaGetSymbolAddress((void**)&alo,   g_alo);
    cudaGetSymbolAddress((void**)&whi,   g_whi);
    cudaGetSymbolAddress((void**)&wlo,   g_wlo);
    cudaGetSymbolAddress((void**)&bias,  g_bias);

    static int smem_set = 0;
    if (!smem_set) {
        cudaFuncSetAttribute(attn_tc_kernel,
                             cudaFuncAttributeMaxDynamicSharedMemorySize, T_SMEM);
        cudaFuncSetAttribute(gemm_bf16_split,
                             cudaFuncAttributeMaxDynamicSharedMemorySize, G_SMEM);
        smem_set = 1;
    }

    const int n4 = M * DMODEL / 4;

    split_kernel<<<(n4 + 255) / 256, 256>>>(x, ahi, alo, n4);
    conv_wqkv_kernel<<<(3 * DMODEL * 128) / 256, 256>>>(wq, wk, wv, bq, bk, bv,
                                                        whi, wlo, bias);
    dim3 qkv_grid(3 * DMODEL / 128, M / 128);
    gemm_bf16_split<<<qkv_grid, 256, G_SMEM>>>(ahi, alo, whi, wlo, bias,
                                               (float*)nullptr, qkvhi, qkvlo, M);
    dim3 attn_grid(SQ / 128, NH, B);
    attn_tc_kernel<<<attn_grid, 128, T_SMEM>>>(qkvhi, qkvlo, ahi, alo);
    conv_wo_kernel<<<(DMODEL * 128) / 256, 256>>>(wo, whi, wlo);
    dim3 out_grid(DMODEL / 128, M / 128);
    gemm_bf16_split<<<out_grid, 256, G_SMEM>>>(ahi, alo, whi, wlo,
                                               (const float*)nullptr,
                                               (float*)d_out, (__nv_bfloat16*)nullptr,
                                               (__nv_bfloat16*)nullptr, M);
}

// round 11
// speedup vs baseline: 1.3980x; 1.0570x over previous
#include <cuda_runtime.h>
#include <cuda_bf16.h>
#include <cstdint>
#include <math.h>

#define SQ     2048
#define DMODEL 1024
#define NH     16
#define DH     64
#define BMAX   2
#define MMAX   (BMAX * SQ)          // 4096

// ---------------- scratch (__device__ globals, allocation-free) -------------
__device__ __nv_bfloat16  g_qkvhi[3 * MMAX * DMODEL];   // q|k|v hi planes
__device__ __nv_bfloat16  g_qkvlo[3 * MMAX * DMODEL];   // q|k|v lo planes
__device__ __nv_bfloat16  g_ahi[MMAX * DMODEL];         // x split / attn-out split
__device__ __nv_bfloat16  g_alo[MMAX * DMODEL];
__device__ __nv_bfloat16  g_whi[3 * DMODEL * DMODEL];   // weights [N][K]
__device__ __nv_bfloat16  g_wlo[3 * DMODEL * DMODEL];
__device__ float          g_bias[3 * DMODEL];

// ---------------------------------------------------------------------------
__device__ __forceinline__ void bsplit(float x, __nv_bfloat16& h, __nv_bfloat16& l)
{
    h = __float2bfloat16_rn(x);
    l = __float2bfloat16_rn(x - __bfloat162float(h));
}

__device__ __forceinline__ void bpack2(float a, float b, uint32_t& hi, uint32_t& lo)
{
    __nv_bfloat16 ha = __float2bfloat16_rn(a), hb = __float2bfloat16_rn(b);
    __nv_bfloat162 H; H.x = ha; H.y = hb;
    __nv_bfloat162 L;
    L.x = __float2bfloat16_rn(a - __bfloat162float(ha));
    L.y = __float2bfloat16_rn(b - __bfloat162float(hb));
    hi = reinterpret_cast<uint32_t&>(H);
    lo = reinterpret_cast<uint32_t&>(L);
}

#define LDSM4(r, a)                                                            \
    asm volatile("ldmatrix.sync.aligned.m8n8.x4.shared.b16 {%0,%1,%2,%3},[%4];"\
                 : "=r"((r)[0]), "=r"((r)[1]), "=r"((r)[2]), "=r"((r)[3])      \
                 : "r"(a))
#define LDSM4T(r, a)                                                           \
    asm volatile("ldmatrix.sync.aligned.m8n8.x4.trans.shared.b16 "             \
                 "{%0,%1,%2,%3},[%4];"                                         \
                 : "=r"((r)[0]), "=r"((r)[1]), "=r"((r)[2]), "=r"((r)[3])      \
                 : "r"(a))
#define MMA16816(d, a, b0, b1)                                                 \
    asm volatile("mma.sync.aligned.m16n8k16.row.col.f32.bf16.bf16.f32 "        \
                 "{%0,%1,%2,%3},{%4,%5,%6,%7},{%8,%9},{%0,%1,%2,%3};"          \
                 : "+f"((d)[0]), "+f"((d)[1]), "+f"((d)[2]), "+f"((d)[3])      \
                 : "r"((a)[0]), "r"((a)[1]), "r"((a)[2]), "r"((a)[3]),         \
                   "r"(b0), "r"(b1))
// L1-caching async copy (R6 lesson: .cg bypasses L1 and regressed)
#define CP16A(dst, src)                                                        \
    asm volatile("cp.async.ca.shared.global [%0],[%1],16;"                     \
                 :: "r"(dst), "l"(src))
#define CP_COMMIT  asm volatile("cp.async.commit_group;")
#define CP_WAIT(n) asm volatile("cp.async.wait_group %0;" :: "n"(n))

extern __shared__ __align__(16) char dynsm[];

// ---------------------------------------------------------------------------
__global__ void split_kernel(const float* __restrict__ in,
                             __nv_bfloat16* __restrict__ hi,
                             __nv_bfloat16* __restrict__ lo, int n4)
{
    int i = blockIdx.x * blockDim.x + threadIdx.x;
    if (i >= n4) return;
    float4 v = ((const float4*)in)[i];
    __nv_bfloat16 h0, h1, h2, h3, l0, l1, l2, l3;
    bsplit(v.x, h0, l0); bsplit(v.y, h1, l1);
    bsplit(v.z, h2, l2); bsplit(v.w, h3, l3);
    ushort4 hv = make_ushort4(__bfloat16_as_ushort(h0), __bfloat16_as_ushort(h1),
                              __bfloat16_as_ushort(h2), __bfloat16_as_ushort(h3));
    ushort4 lv = make_ushort4(__bfloat16_as_ushort(l0), __bfloat16_as_ushort(l1),
                              __bfloat16_as_ushort(l2), __bfloat16_as_ushort(l3));
    ((ushort4*)hi)[i] = hv;
    ((ushort4*)lo)[i] = lv;
}

__global__ void conv_wqkv_kernel(const float* __restrict__ wq, const float* __restrict__ wk,
                                 const float* __restrict__ wv, const float* __restrict__ bq,
                                 const float* __restrict__ bk, const float* __restrict__ bv,
                                 __nv_bfloat16* __restrict__ Whi,
                                 __nv_bfloat16* __restrict__ Wlo,
                                 float* __restrict__ gbias)
{
    int gt = blockIdx.x * 256 + threadIdx.x;
    int n  = gt >> 7;
    int d0 = (gt & 127) << 3;
    const float* w  = (n < 1024) ? wq : (n < 2048 ? wk : wv);
    const float* bb = (n < 1024) ? bq : (n < 2048 ? bk : bv);
    int nn = n & 1023, h = nn >> 6, e = nn & 63;
    const float* src = w + h * (DMODEL * DH) + e;

    __nv_bfloat16 hi[8], lo[8];
#pragma unroll
    for (int i = 0; i < 8; i++)
        bsplit(src[(size_t)(d0 + i) * DH], hi[i], lo[i]);

    size_t o = (size_t)n * DMODEL + d0;
    *(uint4*)(Whi + o) = *(const uint4*)hi;
    *(uint4*)(Wlo + o) = *(const uint4*)lo;
    if (d0 == 0) gbias[n] = bb[nn];
}

__global__ void conv_wo_kernel(const float* __restrict__ wo,
                               __nv_bfloat16* __restrict__ Whi,
                               __nv_bfloat16* __restrict__ Wlo)
{
    int gt = blockIdx.x * 256 + threadIdx.x;
    int n  = gt >> 7;
    int d0 = (gt & 127) << 3;
    __nv_bfloat16 hi[8], lo[8];
#pragma unroll
    for (int i = 0; i < 8; i++)
        bsplit(wo[(size_t)(d0 + i) * DMODEL + n], hi[i], lo[i]);
    size_t o = (size_t)n * DMODEL + d0;
    *(uint4*)(Whi + o) = *(const uint4*)hi;
    *(uint4*)(Wlo + o) = *(const uint4*)lo;
}

// ---------------------------------------------------------------------------
// Fused-pass tensor-core GEMM: per k-block load Ahi/Alo/Whi/Wlo tiles ONCE,
// issue all three split products. 2-stage cp.async.ca pipeline.
// MMA order: pass-outer -> same-accumulator distance 4 (ILP).
// ---------------------------------------------------------------------------
#define G_AH 0
#define G_AL 10240
#define G_BH 20480
#define G_BL 30720
#define G_STG 40960
#define G_SMEM 81920

__global__ __launch_bounds__(256)
void gemm_bf16_split(const __nv_bfloat16* __restrict__ Ahi,
                     const __nv_bfloat16* __restrict__ Alo,
                     const __nv_bfloat16* __restrict__ Whi,
                     const __nv_bfloat16* __restrict__ Wlo,
                     const float* __restrict__ bias,
                     float* __restrict__ C,
                     __nv_bfloat16* __restrict__ Chi,
                     __nv_bfloat16* __restrict__ Clo, int M)
{
    const int tid  = threadIdx.x;
    const int lane = tid & 31;
    const int wid  = tid >> 5;
    const int wm   = (wid & 3) * 32;
    const int wn   = (wid >> 2) * 64;
    const int m0   = blockIdx.y * 128;
    const int n0   = blockIdx.x * 128;

    const int lrow = tid >> 2;          // 0..63
    const int lcol = (tid & 3) * 8;     // 0..24

    float acc[2][8][4];
#pragma unroll
    for (int i = 0; i < 2; i++)
#pragma unroll
        for (int j = 0; j < 8; j++)
#pragma unroll
            for (int c = 0; c < 4; c++) acc[i][j][c] = 0.f;

    const uint32_t sb = (uint32_t)__cvta_generic_to_shared(dynsm);
    uint32_t a_off[2], b_off[4];
#pragma unroll
    for (int mi = 0; mi < 2; mi++)
        a_off[mi] = (uint32_t)((wm + mi * 16 + (lane & 15)) * 40
                               + (lane >> 4) * 8) * 2;
#pragma unroll
    for (int np = 0; np < 4; np++) {
        int g = lane >> 3, r = lane & 7;
        b_off[np] = (uint32_t)((wn + np * 16 + (g >> 1) * 8 + r) * 40
                               + (g & 1) * 8) * 2;
    }
    const uint32_t ld_off = (uint32_t)(lrow * 40 + lcol) * 2;
    const uint32_t row64  = 64 * 40 * 2;

    auto issue = [&](int blk) {
        const int k0 = blk << 5;
        const __nv_bfloat16* agh = Ahi + (size_t)(m0 + lrow) * DMODEL + lcol + k0;
        const __nv_bfloat16* agl = Alo + (size_t)(m0 + lrow) * DMODEL + lcol + k0;
        const __nv_bfloat16* bgh = Whi + (size_t)(n0 + lrow) * DMODEL + lcol + k0;
        const __nv_bfloat16* bgl = Wlo + (size_t)(n0 + lrow) * DMODEL + lcol + k0;
        const uint32_t s = sb + (blk & 1) * G_STG + ld_off;
        CP16A(s + G_AH,         agh);
        CP16A(s + G_AH + row64, agh + (size_t)64 * DMODEL);
        CP16A(s + G_AL,         agl);
        CP16A(s + G_AL + row64, agl + (size_t)64 * DMODEL);
        CP16A(s + G_BH,         bgh);
        CP16A(s + G_BH + row64, bgh + (size_t)64 * DMODEL);
        CP16A(s + G_BL,         bgl);
        CP16A(s + G_BL + row64, bgl + (size_t)64 * DMODEL);
        CP_COMMIT;
    };

    issue(0);
    issue(1);

    for (int blk = 0; blk < 32; blk++) {
        if (blk == 31) { CP_WAIT(0); } else { CP_WAIT(1); }
        __syncthreads();
        const uint32_t so = sb + (blk & 1) * G_STG;

#pragma unroll
        for (int ks = 0; ks < 32; ks += 16) {
            uint32_t afh[2][4], afl[2][4];
#pragma unroll
            for (int mi = 0; mi < 2; mi++) {
                LDSM4(afh[mi], so + G_AH + a_off[mi] + ks * 2);
                LDSM4(afl[mi], so + G_AL + a_off[mi] + ks * 2);
            }
#pragma unroll
            for (int np = 0; np < 4; np++) {
                uint32_t bfh[4], bfl[4];
                LDSM4(bfh, so + G_BH + b_off[np] + ks * 2);
                LDSM4(bfl, so + G_BL + b_off[np] + ks * 2);
                // pass-outer ordering: same-acc distance 4
#pragma unroll
                for (int mi = 0; mi < 2; mi++) {
                    MMA16816(acc[mi][np * 2],     afh[mi], bfh[0], bfh[1]);
                    MMA16816(acc[mi][np * 2 + 1], afh[mi], bfh[2], bfh[3]);
                }
#pragma unroll
                for (int mi = 0; mi < 2; mi++) {
                    MMA16816(acc[mi][np * 2],     afl[mi], bfh[0], bfh[1]);
                    MMA16816(acc[mi][np * 2 + 1], afl[mi], bfh[2], bfh[3]);
                }
#pragma unroll
                for (int mi = 0; mi < 2; mi++) {
                    MMA16816(acc[mi][np * 2],     afh[mi], bfl[0], bfl[1]);
                    MMA16816(acc[mi][np * 2 + 1], afh[mi], bfl[2], bfl[3]);
                }
            }
        }
        __syncthreads();
        if (blk + 2 < 32) issue(blk + 2);
    }

    const size_t plane = (size_t)M * DMODEL;
#pragma unroll
    for (int mi = 0; mi < 2; mi++) {
        int row = m0 + wm + mi * 16 + (lane >> 2);
#pragma unroll
        for (int ni = 0; ni < 8; ni++) {
            int col = n0 + wn + ni * 8 + (lane & 3) * 2;
            float b0 = bias ? bias[col]     : 0.f;
            float b1 = bias ? bias[col + 1] : 0.f;
            float v0 = acc[mi][ni][0] + b0, v1 = acc[mi][ni][1] + b1;
            float v2 = acc[mi][ni][2] + b0, v3 = acc[mi][ni][3] + b1;
            size_t o = (size_t)(col >> 10) * plane
                     + (size_t)row * DMODEL + (col & 1023);
            if (Chi) {
                uint32_t h01, l01, h23, l23;
                bpack2(v0, v1, h01, l01);
                bpack2(v2, v3, h23, l23);
                *(uint32_t*)(Chi + o)               = h01;
                *(uint32_t*)(Clo + o)               = l01;
                *(uint32_t*)(Chi + o + 8 * DMODEL)  = h23;
                *(uint32_t*)(Clo + o + 8 * DMODEL)  = l23;
            } else {
                *(float2*)(C + o)              = make_float2(v0, v1);
                *(float2*)(C + o + 8 * DMODEL) = make_float2(v2, v3);
            }
        }
    }
}

// ---------------------------------------------------------------------------
// Tensor-core flash attention, 128-query CTAs, sync LDG+STS tile loads
// (R9 structure — proven faster than cp.async here). MMA streams reordered
// for accumulator ILP: QK t-outer (distance 2), PV 2-nf groups with
// pass-outer ordering (distance 4). Per-accumulator order preserved ->
// numerics identical to R9/R10.
// Dynamic smem 72 KB: Kh,Kl,Vh,Vl (64x72) + Qh,Ql (128x72).
// ---------------------------------------------------------------------------
#define A_OFF_KH 0
#define A_OFF_KL 9216
#define A_OFF_VH 18432
#define A_OFF_VL 27648
#define A_OFF_QH 36864
#define A_OFF_QL 55296
#define A_SMEM   73728

__global__ __launch_bounds__(128, 2)
void attn_tc_kernel(const __nv_bfloat16* __restrict__ Phi,
                    const __nv_bfloat16* __restrict__ Plo,
                    __nv_bfloat16* __restrict__ Ohi,
                    __nv_bfloat16* __restrict__ Olo)
{
    const int tid  = threadIdx.x;
    const int lane = tid & 31;
    const int w    = tid >> 5;
    const int hh   = blockIdx.y;
    const int b    = blockIdx.z;
    const int q0   = blockIdx.x * 128;
    const float SC = 0.18033688f;     // 0.125 * log2(e)

    const size_t plane = (size_t)gridDim.z * SQ * DMODEL;
    const __nv_bfloat16* Qh = Phi;
    const __nv_bfloat16* Ql = Plo;
    const __nv_bfloat16* Kh = Phi + plane;
    const __nv_bfloat16* Kl = Plo + plane;
    const __nv_bfloat16* Vh = Phi + 2 * plane;
    const __nv_bfloat16* Vl = Plo + 2 * plane;

    const int ldr = tid >> 1;           // 0..63
    const int ldc = (tid & 1) * 32;     // 0/32
    const size_t gb = ((size_t)b * SQ) * DMODEL + hh * DH;

    const uint32_t sb = (uint32_t)__cvta_generic_to_shared(dynsm);

    // ---- stage Q (128 rows, hi+lo) into persistent smem ----
#pragma unroll
    for (int half = 0; half < 2; half++) {
        const int row = half * 64 + ldr;
        const __nv_bfloat16* sh = Qh + gb + (size_t)(q0 + row) * DMODEL + ldc;
        const __nv_bfloat16* sl = Ql + gb + (size_t)(q0 + row) * DMODEL + ldc;
        __nv_bfloat16* dh = (__nv_bfloat16*)(dynsm + A_OFF_QH) + row * 72 + ldc;
        __nv_bfloat16* dl = (__nv_bfloat16*)(dynsm + A_OFF_QL) + row * 72 + ldc;
#pragma unroll
        for (int i = 0; i < 4; i++) {
            *(uint4*)(dh + 8 * i) = *(const uint4*)(sh + 8 * i);
            *(uint4*)(dl + 8 * i) = *(const uint4*)(sl + 8 * i);
        }
    }

    uint32_t qh_addr[2], ql_addr[2];
#pragma unroll
    for (int mi = 0; mi < 2; mi++) {
        uint32_t roff = (uint32_t)((32 * w + 16 * mi + (lane & 15)) * 72
                                   + (lane >> 4) * 8) * 2;
        qh_addr[mi] = sb + A_OFF_QH + roff;
        ql_addr[mi] = sb + A_OFF_QL + roff;
    }

    const uint32_t ka_h = sb + A_OFF_KH + (uint32_t)((lane & 7) * 72 + (lane >> 3) * 8) * 2;
    const uint32_t ka_l = sb + A_OFF_KL + (uint32_t)((lane & 7) * 72 + (lane >> 3) * 8) * 2;
    const uint32_t va_h = sb + A_OFF_VH + (uint32_t)(lane * 72) * 2;
    const uint32_t va_l = sb + A_OFF_VL + (uint32_t)(lane * 72) * 2;

    float oacc[2][8][4];
#pragma unroll
    for (int mi = 0; mi < 2; mi++)
#pragma unroll
        for (int i = 0; i < 8; i++)
#pragma unroll
            for (int c = 0; c < 4; c++) oacc[mi][i][c] = 0.f;
    float mrow[2][2] = {{-1e30f, -1e30f}, {-1e30f, -1e30f}};
    float lsum[2][2] = {{0.f, 0.f}, {0.f, 0.f}};

    for (int kt = 0; kt < SQ; kt += 64) {
        __syncthreads();
        {
            const size_t g = gb + (size_t)(kt + ldr) * DMODEL + ldc;
            __nv_bfloat16* dkh = (__nv_bfloat16*)(dynsm + A_OFF_KH) + ldr * 72 + ldc;
            __nv_bfloat16* dkl = (__nv_bfloat16*)(dynsm + A_OFF_KL) + ldr * 72 + ldc;
            __nv_bfloat16* dvh = (__nv_bfloat16*)(dynsm + A_OFF_VH) + ldr * 72 + ldc;
            __nv_bfloat16* dvl = (__nv_bfloat16*)(dynsm + A_OFF_VL) + ldr * 72 + ldc;
#pragma unroll
            for (int i = 0; i < 4; i++) {
                *(uint4*)(dkh + 8 * i) = *(const uint4*)(Kh + g + 8 * i);
                *(uint4*)(dkl + 8 * i) = *(const uint4*)(Kl + g + 8 * i);
                *(uint4*)(dvh + 8 * i) = *(const uint4*)(Vh + g + 8 * i);
                *(uint4*)(dvl + 8 * i) = *(const uint4*)(Vl + g + 8 * i);
            }
        }
        __syncthreads();

        float sacc[2][8][4];
#pragma unroll
        for (int mi = 0; mi < 2; mi++)
#pragma unroll
            for (int nf = 0; nf < 8; nf++)
#pragma unroll
                for (int c = 0; c < 4; c++) sacc[mi][nf][c] = 0.f;

        // ---- sweep A: qh * (Kh + Kl), t-outer for acc ILP ----
        uint32_t qf[2][4][4];
#pragma unroll
        for (int mi = 0; mi < 2; mi++)
#pragma unroll
            for (int t = 0; t < 4; t++) LDSM4(qf[mi][t], qh_addr[mi] + t * 32);
#pragma unroll
        for (int nf = 0; nf < 8; nf++) {
            uint32_t bh[8], bl[8];
            LDSM4(&bh[0], ka_h + nf * 1152);
            LDSM4(&bh[4], ka_h + nf * 1152 + 64);
            LDSM4(&bl[0], ka_l + nf * 1152);
            LDSM4(&bl[4], ka_l + nf * 1152 + 64);
#pragma unroll
            for (int t = 0; t < 4; t++) {
#pragma unroll
                for (int mi = 0; mi < 2; mi++)
                    MMA16816(sacc[mi][nf], qf[mi][t], bh[2 * t], bh[2 * t + 1]);
#pragma unroll
                for (int mi = 0; mi < 2; mi++)
                    MMA16816(sacc[mi][nf], qf[mi][t], bl[2 * t], bl[2 * t + 1]);
            }
        }
        // ---- sweep B: ql * Kh ----
#pragma unroll
        for (int mi = 0; mi < 2; mi++)
#pragma unroll
            for (int t = 0; t < 4; t++) LDSM4(qf[mi][t], ql_addr[mi] + t * 32);
#pragma unroll
        for (int nf = 0; nf < 8; nf++) {
            uint32_t bh[8];
            LDSM4(&bh[0], ka_h + nf * 1152);
            LDSM4(&bh[4], ka_h + nf * 1152 + 64);
#pragma unroll
            for (int t = 0; t < 4; t++)
#pragma unroll
                for (int mi = 0; mi < 2; mi++)
                    MMA16816(sacc[mi][nf], qf[mi][t], bh[2 * t], bh[2 * t + 1]);
        }

        // ---- online softmax (base-2 domain), per m-tile ----
        uint32_t ah[2][4][4], al[2][4][4];
#pragma unroll
        for (int mi = 0; mi < 2; mi++) {
#pragma unroll
            for (int nf = 0; nf < 8; nf++)
#pragma unroll
                for (int c = 0; c < 4; c++) sacc[mi][nf][c] *= SC;
            float tmax0 = -1e30f, tmax1 = -1e30f;
#pragma unroll
            for (int nf = 0; nf < 8; nf++) {
                tmax0 = fmaxf(tmax0, fmaxf(sacc[mi][nf][0], sacc[mi][nf][1]));
                tmax1 = fmaxf(tmax1, fmaxf(sacc[mi][nf][2], sacc[mi][nf][3]));
            }
#pragma unroll
            for (int off = 1; off <= 2; off <<= 1) {
                tmax0 = fmaxf(tmax0, __shfl_xor_sync(0xffffffffu, tmax0, off));
                tmax1 = fmaxf(tmax1, __shfl_xor_sync(0xffffffffu, tmax1, off));
            }
            float m0n = fmaxf(mrow[mi][0], tmax0);
            float m1n = fmaxf(mrow[mi][1], tmax1);
            float c0 = exp2f(mrow[mi][0] - m0n);
            float c1 = exp2f(mrow[mi][1] - m1n);
            mrow[mi][0] = m0n; mrow[mi][1] = m1n;
            lsum[mi][0] *= c0;  lsum[mi][1] *= c1;
#pragma unroll
            for (int nf = 0; nf < 8; nf++) {
                oacc[mi][nf][0] *= c0; oacc[mi][nf][1] *= c0;
                oacc[mi][nf][2] *= c1; oacc[mi][nf][3] *= c1;
            }
            float s0 = 0.f, s1 = 0.f;
#pragma unroll
            for (int nf = 0; nf < 8; nf++) {
                float p0 = exp2f(sacc[mi][nf][0] - m0n);
                float p1 = exp2f(sacc[mi][nf][1] - m0n);
                float p2 = exp2f(sacc[mi][nf][2] - m1n);
                float p3 = exp2f(sacc[mi][nf][3] - m1n);
                sacc[mi][nf][0] = p0; sacc[mi][nf][1] = p1;
                sacc[mi][nf][2] = p2; sacc[mi][nf][3] = p3;
                s0 += p0 + p1; s1 += p2 + p3;
            }
#pragma unroll
            for (int off = 1; off <= 2; off <<= 1) {
                s0 += __shfl_xor_sync(0xffffffffu, s0, off);
                s1 += __shfl_xor_sync(0xffffffffu, s1, off);
            }
            lsum[mi][0] += s0; lsum[mi][1] += s1;

#pragma unroll
            for (int t = 0; t < 4; t++) {
                bpack2(sacc[mi][2 * t][0],     sacc[mi][2 * t][1],     ah[mi][t][0], al[mi][t][0]);
                bpack2(sacc[mi][2 * t][2],     sacc[mi][2 * t][3],     ah[mi][t][1], al[mi][t][1]);
                bpack2(sacc[mi][2 * t + 1][0], sacc[mi][2 * t + 1][1], ah[mi][t][2], al[mi][t][2]);
                bpack2(sacc[mi][2 * t + 1][2], sacc[mi][2 * t + 1][3], ah[mi][t][3], al[mi][t][3]);
            }
        }

        // ---- O += P V: 2-nf groups, pass-outer (same-acc distance 4) ----
#pragma unroll
        for (int nfp = 0; nfp < 4; nfp++) {
            uint32_t vh[2][8], vl[2][8];
#pragma unroll
            for (int n2 = 0; n2 < 2; n2++) {
                const int nf = nfp * 2 + n2;
                LDSM4T(&vh[n2][0], va_h + nf * 16);
                LDSM4T(&vh[n2][4], va_h + nf * 16 + 32 * 144);
                LDSM4T(&vl[n2][0], va_l + nf * 16);
                LDSM4T(&vl[n2][4], va_l + nf * 16 + 32 * 144);
            }
#pragma unroll
            for (int t = 0; t < 4; t++) {
#pragma unroll
                for (int mi = 0; mi < 2; mi++)
#pragma unroll
                    for (int n2 = 0; n2 < 2; n2++)
                        MMA16816(oacc[mi][nfp * 2 + n2], ah[mi][t],
                                 vh[n2][2 * t], vh[n2][2 * t + 1]);
#pragma unroll
                for (int mi = 0; mi < 2; mi++)
#pragma unroll
                    for (int n2 = 0; n2 < 2; n2++)
                        MMA16816(oacc[mi][nfp * 2 + n2], al[mi][t],
                                 vh[n2][2 * t], vh[n2][2 * t + 1]);
#pragma unroll
                for (int mi = 0; mi < 2; mi++)
#pragma unroll
                    for (int n2 = 0; n2 < 2; n2++)
                        MMA16816(oacc[mi][nfp * 2 + n2], ah[mi][t],
                                 vl[n2][2 * t], vl[n2][2 * t + 1]);
            }
        }
    }

    // ---- epilogue ----
    const int r  = lane >> 2;
    const int c2 = (lane & 3) * 2;
#pragma unroll
    for (int mi = 0; mi < 2; mi++) {
        const float inv0 = 1.0f / lsum[mi][0];
        const float inv1 = 1.0f / lsum[mi][1];
        const int qrow = q0 + 32 * w + 16 * mi + r;
        const size_t ob = ((size_t)(b * SQ + qrow)) * DMODEL + hh * DH + c2;
#pragma unroll
        for (int nf = 0; nf < 8; nf++) {
            uint32_t h01, l01, h23, l23;
            bpack2(oacc[mi][nf][0] * inv0, oacc[mi][nf][1] * inv0, h01, l01);
            bpack2(oacc[mi][nf][2] * inv1, oacc[mi][nf][3] * inv1, h23, l23);
            size_t o = ob + nf * 8;
            *(uint32_t*)(Ohi + o)              = h01;
            *(uint32_t*)(Olo + o)              = l01;
            *(uint32_t*)(Ohi + o + 8 * DMODEL) = h23;
            *(uint32_t*)(Olo + o + 8 * DMODEL) = l23;
        }
    }
}

// ---------------------------------------------------------------------------
extern "C" void kernel_launch(void* const* d_in, const int* in_sizes, int n_in,
                              void* d_out, int out_size)
{
    const float* x  = (const float*)d_in[0];
    const float* wq = (const float*)d_in[2];
    const float* bq = (const float*)d_in[3];
    const float* wk = (const float*)d_in[4];
    const float* bk = (const float*)d_in[5];
    const float* wv = (const float*)d_in[6];
    const float* bv = (const float*)d_in[7];
    const float* wo = (const float*)d_in[8];

    const int B = in_sizes[0] / (SQ * DMODEL);   // 2
    const int M = B * SQ;                        // 4096

    __nv_bfloat16 *qkvhi, *qkvlo, *ahi, *alo, *whi, *wlo;
    float* bias;
    cudaGetSymbolAddress((void**)&qkvhi, g_qkvhi);
    cudaGetSymbolAddress((void**)&qkvlo, g_qkvlo);
    cudaGetSymbolAddress((void**)&ahi,   g_ahi);
    cudaGetSymbolAddress((void**)&alo,   g_alo);
    cudaGetSymbolAddress((void**)&whi,   g_whi);
    cudaGetSymbolAddress((void**)&wlo,   g_wlo);
    cudaGetSymbolAddress((void**)&bias,  g_bias);

    static int smem_set = 0;
    if (!smem_set) {
        cudaFuncSetAttribute(attn_tc_kernel,
                             cudaFuncAttributeMaxDynamicSharedMemorySize, A_SMEM);
        cudaFuncSetAttribute(gemm_bf16_split,
                             cudaFuncAttributeMaxDynamicSharedMemorySize, G_SMEM);
        smem_set = 1;
    }

    const int n4 = M * DMODEL / 4;

    split_kernel<<<(n4 + 255) / 256, 256>>>(x, ahi, alo, n4);
    conv_wqkv_kernel<<<(3 * DMODEL * 128) / 256, 256>>>(wq, wk, wv, bq, bk, bv,
                                                        whi, wlo, bias);
    dim3 qkv_grid(3 * DMODEL / 128, M / 128);
    gemm_bf16_split<<<qkv_grid, 256, G_SMEM>>>(ahi, alo, whi, wlo, bias,
                                               (float*)nullptr, qkvhi, qkvlo, M);
    dim3 attn_grid(SQ / 128, NH, B);
    attn_tc_kernel<<<attn_grid, 128, A_SMEM>>>(qkvhi, qkvlo, ahi, alo);
    conv_wo_kernel<<<(DMODEL * 128) / 256, 256>>>(wo, whi, wlo);
    dim3 out_grid(DMODEL / 128, M / 128);
    gemm_bf16_split<<<out_grid, 256, G_SMEM>>>(ahi, alo, whi, wlo,
                                               (const float*)nullptr,
                                               (float*)d_out, (__nv_bfloat16*)nullptr,
                                               (__nv_bfloat16*)nullptr, M);
}

// round 12
// speedup vs baseline: 1.6633x; 1.1898x over previous
#include <cuda_runtime.h>
#include <cuda_fp16.h>
#include <cstdint>
#include <math.h>

#define SQ     2048
#define DMODEL 1024
#define NH     16
#define DH     64
#define BMAX   2
#define MMAX   (BMAX * SQ)          // 4096

// ---------------- scratch (__device__ globals, allocation-free) -------------
__device__ __half  g_qkvhi[3 * MMAX * DMODEL];   // q|k|v hi planes
__device__ __half  g_qkvlo[3 * MMAX * DMODEL];   // q|k|v lo planes
__device__ __half  g_ahi[MMAX * DMODEL];         // x split / attn-out split
__device__ __half  g_alo[MMAX * DMODEL];
__device__ __half  g_whi[3 * DMODEL * DMODEL];   // weights [N][K]
__device__ __half  g_wlo[3 * DMODEL * DMODEL];
__device__ float   g_bias[3 * DMODEL];

// ---------------------------------------------------------------------------
__device__ __forceinline__ void hsplit(float x, __half& h, __half& l)
{
    h = __float2half_rn(x);
    l = __float2half_rn(x - __half2float(h));
}

// (a,b) -> fp16x2 hi word + fp16x2 residual word
__device__ __forceinline__ void hpack2(float a, float b, uint32_t& hi, uint32_t& lo)
{
    __half2 H = __floats2half2_rn(a, b);
    __half2 L = __floats2half2_rn(a - __half2float(__low2half(H)),
                                  b - __half2float(__high2half(H)));
    hi = reinterpret_cast<uint32_t&>(H);
    lo = reinterpret_cast<uint32_t&>(L);
}

// (a,b) -> fp16x2 word (no residual)
__device__ __forceinline__ uint32_t hpair(float a, float b)
{
    __half2 H = __floats2half2_rn(a, b);
    return reinterpret_cast<uint32_t&>(H);
}

#define LDSM4(r, a)                                                            \
    asm volatile("ldmatrix.sync.aligned.m8n8.x4.shared.b16 {%0,%1,%2,%3},[%4];"\
                 : "=r"((r)[0]), "=r"((r)[1]), "=r"((r)[2]), "=r"((r)[3])      \
                 : "r"(a))
#define LDSM4T(r, a)                                                           \
    asm volatile("ldmatrix.sync.aligned.m8n8.x4.trans.shared.b16 "             \
                 "{%0,%1,%2,%3},[%4];"                                         \
                 : "=r"((r)[0]), "=r"((r)[1]), "=r"((r)[2]), "=r"((r)[3])      \
                 : "r"(a))
#define MMA16816(d, a, b0, b1)                                                 \
    asm volatile("mma.sync.aligned.m16n8k16.row.col.f32.f16.f16.f32 "          \
                 "{%0,%1,%2,%3},{%4,%5,%6,%7},{%8,%9},{%0,%1,%2,%3};"          \
                 : "+f"((d)[0]), "+f"((d)[1]), "+f"((d)[2]), "+f"((d)[3])      \
                 : "r"((a)[0]), "r"((a)[1]), "r"((a)[2]), "r"((a)[3]),         \
                   "r"(b0), "r"(b1))
// L1-caching async copy (R6 lesson: .cg bypasses L1 and regressed)
#define CP16A(dst, src)                                                        \
    asm volatile("cp.async.ca.shared.global [%0],[%1],16;"                     \
                 :: "r"(dst), "l"(src))
#define CP_COMMIT  asm volatile("cp.async.commit_group;")
#define CP_WAIT(n) asm volatile("cp.async.wait_group %0;" :: "n"(n))

extern __shared__ __align__(16) char dynsm[];

// ---------------------------------------------------------------------------
__global__ void split_kernel(const float* __restrict__ in,
                             __half* __restrict__ hi,
                             __half* __restrict__ lo, int n4)
{
    int i = blockIdx.x * blockDim.x + threadIdx.x;
    if (i >= n4) return;
    float4 v = ((const float4*)in)[i];
    __half h0, h1, h2, h3, l0, l1, l2, l3;
    hsplit(v.x, h0, l0); hsplit(v.y, h1, l1);
    hsplit(v.z, h2, l2); hsplit(v.w, h3, l3);
    ushort4 hv = make_ushort4(__half_as_ushort(h0), __half_as_ushort(h1),
                              __half_as_ushort(h2), __half_as_ushort(h3));
    ushort4 lv = make_ushort4(__half_as_ushort(l0), __half_as_ushort(l1),
                              __half_as_ushort(l2), __half_as_ushort(l3));
    ((ushort4*)hi)[i] = hv;
    ((ushort4*)lo)[i] = lv;
}

__global__ void conv_wqkv_kernel(const float* __restrict__ wq, const float* __restrict__ wk,
                                 const float* __restrict__ wv, const float* __restrict__ bq,
                                 const float* __restrict__ bk, const float* __restrict__ bv,
                                 __half* __restrict__ Whi,
                                 __half* __restrict__ Wlo,
                                 float* __restrict__ gbias)
{
    int gt = blockIdx.x * 256 + threadIdx.x;
    int n  = gt >> 7;
    int d0 = (gt & 127) << 3;
    const float* w  = (n < 1024) ? wq : (n < 2048 ? wk : wv);
    const float* bb = (n < 1024) ? bq : (n < 2048 ? bk : bv);
    int nn = n & 1023, h = nn >> 6, e = nn & 63;
    const float* src = w + h * (DMODEL * DH) + e;

    __half hi[8], lo[8];
#pragma unroll
    for (int i = 0; i < 8; i++)
        hsplit(src[(size_t)(d0 + i) * DH], hi[i], lo[i]);

    size_t o = (size_t)n * DMODEL + d0;
    *(uint4*)(Whi + o) = *(const uint4*)hi;
    *(uint4*)(Wlo + o) = *(const uint4*)lo;
    if (d0 == 0) gbias[n] = bb[nn];
}

// Wo: 2-pass GEMM needs only hi plane
__global__ void conv_wo_kernel(const float* __restrict__ wo,
                               __half* __restrict__ Whi)
{
    int gt = blockIdx.x * 256 + threadIdx.x;
    int n  = gt >> 7;
    int d0 = (gt & 127) << 3;
    __half hi[8];
#pragma unroll
    for (int i = 0; i < 8; i++)
        hi[i] = __float2half_rn(wo[(size_t)(d0 + i) * DMODEL + n]);
    *(uint4*)(Whi + (size_t)n * DMODEL + d0) = *(const uint4*)hi;
}

// ---------------------------------------------------------------------------
// Fused-pass tensor-core GEMM, fp16 split, fp32 accumulate.
// Passes: (1) ah*bh  (2) al*bh  (3) ah*bl -- pass 3 only when n0 < n3lim
// (Q/K projection columns need 21-bit effective precision; V and out-proj
// tolerate 2-pass). 2-stage cp.async.ca pipeline.
// ---------------------------------------------------------------------------
#define G_AH 0
#define G_AL 10240
#define G_BH 20480
#define G_BL 30720
#define G_STG 40960
#define G_SMEM 81920

__global__ __launch_bounds__(256)
void gemm_fp16_split(const __half* __restrict__ Ahi,
                     const __half* __restrict__ Alo,
                     const __half* __restrict__ Whi,
                     const __half* __restrict__ Wlo,
                     const float* __restrict__ bias,
                     float* __restrict__ C,
                     __half* __restrict__ Chi,
                     __half* __restrict__ Clo, int M, int n3lim)
{
    const int tid  = threadIdx.x;
    const int lane = tid & 31;
    const int wid  = tid >> 5;
    const int wm   = (wid & 3) * 32;
    const int wn   = (wid >> 2) * 64;
    const int m0   = blockIdx.y * 128;
    const int n0   = blockIdx.x * 128;
    const bool p3  = (n0 < n3lim);

    const int lrow = tid >> 2;          // 0..63
    const int lcol = (tid & 3) * 8;     // 0..24

    float acc[2][8][4];
#pragma unroll
    for (int i = 0; i < 2; i++)
#pragma unroll
        for (int j = 0; j < 8; j++)
#pragma unroll
            for (int c = 0; c < 4; c++) acc[i][j][c] = 0.f;

    const uint32_t sb = (uint32_t)__cvta_generic_to_shared(dynsm);
    uint32_t a_off[2], b_off[4];
#pragma unroll
    for (int mi = 0; mi < 2; mi++)
        a_off[mi] = (uint32_t)((wm + mi * 16 + (lane & 15)) * 40
                               + (lane >> 4) * 8) * 2;
#pragma unroll
    for (int np = 0; np < 4; np++) {
        int g = lane >> 3, r = lane & 7;
        b_off[np] = (uint32_t)((wn + np * 16 + (g >> 1) * 8 + r) * 40
                               + (g & 1) * 8) * 2;
    }
    const uint32_t ld_off = (uint32_t)(lrow * 40 + lcol) * 2;
    const uint32_t row64  = 64 * 40 * 2;

    auto issue = [&](int blk) {
        const int k0 = blk << 5;
        const __half* agh = Ahi + (size_t)(m0 + lrow) * DMODEL + lcol + k0;
        const __half* agl = Alo + (size_t)(m0 + lrow) * DMODEL + lcol + k0;
        const __half* bgh = Whi + (size_t)(n0 + lrow) * DMODEL + lcol + k0;
        const uint32_t s = sb + (blk & 1) * G_STG + ld_off;
        CP16A(s + G_AH,         agh);
        CP16A(s + G_AH + row64, agh + (size_t)64 * DMODEL);
        CP16A(s + G_AL,         agl);
        CP16A(s + G_AL + row64, agl + (size_t)64 * DMODEL);
        CP16A(s + G_BH,         bgh);
        CP16A(s + G_BH + row64, bgh + (size_t)64 * DMODEL);
        if (p3) {
            const __half* bgl = Wlo + (size_t)(n0 + lrow) * DMODEL + lcol + k0;
            CP16A(s + G_BL,         bgl);
            CP16A(s + G_BL + row64, bgl + (size_t)64 * DMODEL);
        }
        CP_COMMIT;
    };

    issue(0);
    issue(1);

    for (int blk = 0; blk < 32; blk++) {
        if (blk == 31) { CP_WAIT(0); } else { CP_WAIT(1); }
        __syncthreads();
        const uint32_t so = sb + (blk & 1) * G_STG;

#pragma unroll
        for (int ks = 0; ks < 32; ks += 16) {
            uint32_t afh[2][4], afl[2][4];
#pragma unroll
            for (int mi = 0; mi < 2; mi++) {
                LDSM4(afh[mi], so + G_AH + a_off[mi] + ks * 2);
                LDSM4(afl[mi], so + G_AL + a_off[mi] + ks * 2);
            }
#pragma unroll
            for (int np = 0; np < 4; np++) {
                uint32_t bfh[4];
                LDSM4(bfh, so + G_BH + b_off[np] + ks * 2);
#pragma unroll
                for (int mi = 0; mi < 2; mi++) {
                    MMA16816(acc[mi][np * 2],     afh[mi], bfh[0], bfh[1]);
                    MMA16816(acc[mi][np * 2 + 1], afh[mi], bfh[2], bfh[3]);
                }
#pragma unroll
                for (int mi = 0; mi < 2; mi++) {
                    MMA16816(acc[mi][np * 2],     afl[mi], bfh[0], bfh[1]);
                    MMA16816(acc[mi][np * 2 + 1], afl[mi], bfh[2], bfh[3]);
                }
                if (p3) {
                    uint32_t bfl[4];
                    LDSM4(bfl, so + G_BL + b_off[np] + ks * 2);
#pragma unroll
                    for (int mi = 0; mi < 2; mi++) {
                        MMA16816(acc[mi][np * 2],     afh[mi], bfl[0], bfl[1]);
                        MMA16816(acc[mi][np * 2 + 1], afh[mi], bfl[2], bfl[3]);
                    }
                }
            }
        }
        __syncthreads();
        if (blk + 2 < 32) issue(blk + 2);
    }

    const size_t plane = (size_t)M * DMODEL;
#pragma unroll
    for (int mi = 0; mi < 2; mi++) {
        int row = m0 + wm + mi * 16 + (lane >> 2);
#pragma unroll
        for (int ni = 0; ni < 8; ni++) {
            int col = n0 + wn + ni * 8 + (lane & 3) * 2;
            float b0 = bias ? bias[col]     : 0.f;
            float b1 = bias ? bias[col + 1] : 0.f;
            float v0 = acc[mi][ni][0] + b0, v1 = acc[mi][ni][1] + b1;
            float v2 = acc[mi][ni][2] + b0, v3 = acc[mi][ni][3] + b1;
            size_t o = (size_t)(col >> 10) * plane
                     + (size_t)row * DMODEL + (col & 1023);
            if (Chi) {
                uint32_t h01, l01, h23, l23;
                hpack2(v0, v1, h01, l01);
                hpack2(v2, v3, h23, l23);
                *(uint32_t*)(Chi + o)               = h01;
                *(uint32_t*)(Clo + o)               = l01;
                *(uint32_t*)(Chi + o + 8 * DMODEL)  = h23;
                *(uint32_t*)(Clo + o + 8 * DMODEL)  = l23;
            } else {
                *(float2*)(C + o)              = make_float2(v0, v1);
                *(float2*)(C + o + 8 * DMODEL) = make_float2(v2, v3);
            }
        }
    }
}

// ---------------------------------------------------------------------------
// Tensor-core flash attention, fp16. 128-query CTAs, sync LDG+STS loads.
// QK: 3-pass (qh*kh + qh*kl, then ql*kh). PV: SINGLE pass (fp16 P, fp16 Vh).
// Dynamic smem 63 KB: Kh,Kl,Vh (64x72) + Qh,Ql (128x72).
// ---------------------------------------------------------------------------
#define A_OFF_KH 0
#define A_OFF_KL 9216
#define A_OFF_VH 18432
#define A_OFF_QH 27648
#define A_OFF_QL 46080
#define A_SMEM   64512

__global__ __launch_bounds__(128, 2)
void attn_tc_kernel(const __half* __restrict__ Phi,
                    const __half* __restrict__ Plo,
                    __half* __restrict__ Ohi,
                    __half* __restrict__ Olo)
{
    const int tid  = threadIdx.x;
    const int lane = tid & 31;
    const int w    = tid >> 5;
    const int hh   = blockIdx.y;
    const int b    = blockIdx.z;
    const int q0   = blockIdx.x * 128;
    const float SC = 0.18033688f;     // 0.125 * log2(e)

    const size_t plane = (size_t)gridDim.z * SQ * DMODEL;
    const __half* Qh = Phi;
    const __half* Ql = Plo;
    const __half* Kh = Phi + plane;
    const __half* Kl = Plo + plane;
    const __half* Vh = Phi + 2 * plane;

    const int ldr = tid >> 1;           // 0..63
    const int ldc = (tid & 1) * 32;     // 0/32
    const size_t gb = ((size_t)b * SQ) * DMODEL + hh * DH;

    const uint32_t sb = (uint32_t)__cvta_generic_to_shared(dynsm);

    // ---- stage Q (128 rows, hi+lo) into persistent smem ----
#pragma unroll
    for (int half = 0; half < 2; half++) {
        const int row = half * 64 + ldr;
        const __half* sh = Qh + gb + (size_t)(q0 + row) * DMODEL + ldc;
        const __half* sl = Ql + gb + (size_t)(q0 + row) * DMODEL + ldc;
        __half* dh = (__half*)(dynsm + A_OFF_QH) + row * 72 + ldc;
        __half* dl = (__half*)(dynsm + A_OFF_QL) + row * 72 + ldc;
#pragma unroll
        for (int i = 0; i < 4; i++) {
            *(uint4*)(dh + 8 * i) = *(const uint4*)(sh + 8 * i);
            *(uint4*)(dl + 8 * i) = *(const uint4*)(sl + 8 * i);
        }
    }

    uint32_t qh_addr[2], ql_addr[2];
#pragma unroll
    for (int mi = 0; mi < 2; mi++) {
        uint32_t roff = (uint32_t)((32 * w + 16 * mi + (lane & 15)) * 72
                                   + (lane >> 4) * 8) * 2;
        qh_addr[mi] = sb + A_OFF_QH + roff;
        ql_addr[mi] = sb + A_OFF_QL + roff;
    }

    const uint32_t ka_h = sb + A_OFF_KH + (uint32_t)((lane & 7) * 72 + (lane >> 3) * 8) * 2;
    const uint32_t ka_l = sb + A_OFF_KL + (uint32_t)((lane & 7) * 72 + (lane >> 3) * 8) * 2;
    const uint32_t va_h = sb + A_OFF_VH + (uint32_t)(lane * 72) * 2;

    float oacc[2][8][4];
#pragma unroll
    for (int mi = 0; mi < 2; mi++)
#pragma unroll
        for (int i = 0; i < 8; i++)
#pragma unroll
            for (int c = 0; c < 4; c++) oacc[mi][i][c] = 0.f;
    float mrow[2][2] = {{-1e30f, -1e30f}, {-1e30f, -1e30f}};
    float lsum[2][2] = {{0.f, 0.f}, {0.f, 0.f}};

    for (int kt = 0; kt < SQ; kt += 64) {
        __syncthreads();
        {
            const size_t g = gb + (size_t)(kt + ldr) * DMODEL + ldc;
            __half* dkh = (__half*)(dynsm + A_OFF_KH) + ldr * 72 + ldc;
            __half* dkl = (__half*)(dynsm + A_OFF_KL) + ldr * 72 + ldc;
            __half* dvh = (__half*)(dynsm + A_OFF_VH) + ldr * 72 + ldc;
#pragma unroll
            for (int i = 0; i < 4; i++) {
                *(uint4*)(dkh + 8 * i) = *(const uint4*)(Kh + g + 8 * i);
                *(uint4*)(dkl + 8 * i) = *(const uint4*)(Kl + g + 8 * i);
                *(uint4*)(dvh + 8 * i) = *(const uint4*)(Vh + g + 8 * i);
            }
        }
        __syncthreads();

        float sacc[2][8][4];
#pragma unroll
        for (int mi = 0; mi < 2; mi++)
#pragma unroll
            for (int nf = 0; nf < 8; nf++)
#pragma unroll
                for (int c = 0; c < 4; c++) sacc[mi][nf][c] = 0.f;

        // ---- sweep A: qh * (Kh + Kl), t-outer for acc ILP ----
        uint32_t qf[2][4][4];
#pragma unroll
        for (int mi = 0; mi < 2; mi++)
#pragma unroll
            for (int t = 0; t < 4; t++) LDSM4(qf[mi][t], qh_addr[mi] + t * 32);
#pragma unroll
        for (int nf = 0; nf < 8; nf++) {
            uint32_t bh[8], bl[8];
            LDSM4(&bh[0], ka_h + nf * 1152);
            LDSM4(&bh[4], ka_h + nf * 1152 + 64);
            LDSM4(&bl[0], ka_l + nf * 1152);
            LDSM4(&bl[4], ka_l + nf * 1152 + 64);
#pragma unroll
            for (int t = 0; t < 4; t++) {
#pragma unroll
                for (int mi = 0; mi < 2; mi++)
                    MMA16816(sacc[mi][nf], qf[mi][t], bh[2 * t], bh[2 * t + 1]);
#pragma unroll
                for (int mi = 0; mi < 2; mi++)
                    MMA16816(sacc[mi][nf], qf[mi][t], bl[2 * t], bl[2 * t + 1]);
            }
        }
        // ---- sweep B: ql * Kh ----
#pragma unroll
        for (int mi = 0; mi < 2; mi++)
#pragma unroll
            for (int t = 0; t < 4; t++) LDSM4(qf[mi][t], ql_addr[mi] + t * 32);
#pragma unroll
        for (int nf = 0; nf < 8; nf++) {
            uint32_t bh[8];
            LDSM4(&bh[0], ka_h + nf * 1152);
            LDSM4(&bh[4], ka_h + nf * 1152 + 64);
#pragma unroll
            for (int t = 0; t < 4; t++)
#pragma unroll
                for (int mi = 0; mi < 2; mi++)
                    MMA16816(sacc[mi][nf], qf[mi][t], bh[2 * t], bh[2 * t + 1]);
        }

        // ---- online softmax (base-2 domain), per m-tile ----
        uint32_t ah[2][4][4];
#pragma unroll
        for (int mi = 0; mi < 2; mi++) {
#pragma unroll
            for (int nf = 0; nf < 8; nf++)
#pragma unroll
                for (int c = 0; c < 4; c++) sacc[mi][nf][c] *= SC;
            float tmax0 = -1e30f, tmax1 = -1e30f;
#pragma unroll
            for (int nf = 0; nf < 8; nf++) {
                tmax0 = fmaxf(tmax0, fmaxf(sacc[mi][nf][0], sacc[mi][nf][1]));
                tmax1 = fmaxf(tmax1, fmaxf(sacc[mi][nf][2], sacc[mi][nf][3]));
            }
#pragma unroll
            for (int off = 1; off <= 2; off <<= 1) {
                tmax0 = fmaxf(tmax0, __shfl_xor_sync(0xffffffffu, tmax0, off));
                tmax1 = fmaxf(tmax1, __shfl_xor_sync(0xffffffffu, tmax1, off));
            }
            float m0n = fmaxf(mrow[mi][0], tmax0);
            float m1n = fmaxf(mrow[mi][1], tmax1);
            float c0 = exp2f(mrow[mi][0] - m0n);
            float c1 = exp2f(mrow[mi][1] - m1n);
            mrow[mi][0] = m0n; mrow[mi][1] = m1n;
            lsum[mi][0] *= c0;  lsum[mi][1] *= c1;
#pragma unroll
            for (int nf = 0; nf < 8; nf++) {
                oacc[mi][nf][0] *= c0; oacc[mi][nf][1] *= c0;
                oacc[mi][nf][2] *= c1; oacc[mi][nf][3] *= c1;
            }
            float s0 = 0.f, s1 = 0.f;
#pragma unroll
            for (int nf = 0; nf < 8; nf++) {
                float p0 = exp2f(sacc[mi][nf][0] - m0n);
                float p1 = exp2f(sacc[mi][nf][1] - m0n);
                float p2 = exp2f(sacc[mi][nf][2] - m1n);
                float p3 = exp2f(sacc[mi][nf][3] - m1n);
                sacc[mi][nf][0] = p0; sacc[mi][nf][1] = p1;
                sacc[mi][nf][2] = p2; sacc[mi][nf][3] = p3;
                s0 += p0 + p1; s1 += p2 + p3;
            }
#pragma unroll
            for (int off = 1; off <= 2; off <<= 1) {
                s0 += __shfl_xor_sync(0xffffffffu, s0, off);
                s1 += __shfl_xor_sync(0xffffffffu, s1, off);
            }
            lsum[mi][0] += s0; lsum[mi][1] += s1;

            // pack P frags (fp16, no residual needed for single-pass PV)
#pragma unroll
            for (int t = 0; t < 4; t++) {
                ah[mi][t][0] = hpair(sacc[mi][2 * t][0],     sacc[mi][2 * t][1]);
                ah[mi][t][1] = hpair(sacc[mi][2 * t][2],     sacc[mi][2 * t][3]);
                ah[mi][t][2] = hpair(sacc[mi][2 * t + 1][0], sacc[mi][2 * t + 1][1]);
                ah[mi][t][3] = hpair(sacc[mi][2 * t + 1][2], sacc[mi][2 * t + 1][3]);
            }
        }

        // ---- O += P V: single fp16 pass, 2-nf groups (acc distance 4) ----
#pragma unroll
        for (int nfp = 0; nfp < 4; nfp++) {
            uint32_t vh[2][8];
#pragma unroll
            for (int n2 = 0; n2 < 2; n2++) {
                const int nf = nfp * 2 + n2;
                LDSM4T(&vh[n2][0], va_h + nf * 16);
                LDSM4T(&vh[n2][4], va_h + nf * 16 + 32 * 144);
            }
#pragma unroll
            for (int t = 0; t < 4; t++)
#pragma unroll
                for (int mi = 0; mi < 2; mi++)
#pragma unroll
                    for (int n2 = 0; n2 < 2; n2++)
                        MMA16816(oacc[mi][nfp * 2 + n2], ah[mi][t],
                                 vh[n2][2 * t], vh[n2][2 * t + 1]);
        }
    }

    // ---- epilogue: normalize, fp16 hi/lo split for out-projection ----
    const int r  = lane >> 2;
    const int c2 = (lane & 3) * 2;
#pragma unroll
    for (int mi = 0; mi < 2; mi++) {
        const float inv0 = 1.0f / lsum[mi][0];
        const float inv1 = 1.0f / lsum[mi][1];
        const int qrow = q0 + 32 * w + 16 * mi + r;
        const size_t ob = ((size_t)(b * SQ + qrow)) * DMODEL + hh * DH + c2;
#pragma unroll
        for (int nf = 0; nf < 8; nf++) {
            uint32_t h01, l01, h23, l23;
            hpack2(oacc[mi][nf][0] * inv0, oacc[mi][nf][1] * inv0, h01, l01);
            hpack2(oacc[mi][nf][2] * inv1, oacc[mi][nf][3] * inv1, h23, l23);
            size_t o = ob + nf * 8;
            *(uint32_t*)(Ohi + o)              = h01;
            *(uint32_t*)(Olo + o)              = l01;
            *(uint32_t*)(Ohi + o + 8 * DMODEL) = h23;
            *(uint32_t*)(Olo + o + 8 * DMODEL) = l23;
        }
    }
}

// ---------------------------------------------------------------------------
extern "C" void kernel_launch(void* const* d_in, const int* in_sizes, int n_in,
                              void* d_out, int out_size)
{
    const float* x  = (const float*)d_in[0];
    const float* wq = (const float*)d_in[2];
    const float* bq = (const float*)d_in[3];
    const float* wk = (const float*)d_in[4];
    const float* bk = (const float*)d_in[5];
    const float* wv = (const float*)d_in[6];
    const float* bv = (const float*)d_in[7];
    const float* wo = (const float*)d_in[8];

    const int B = in_sizes[0] / (SQ * DMODEL);   // 2
    const int M = B * SQ;                        // 4096

    __half *qkvhi, *qkvlo, *ahi, *alo, *whi, *wlo;
    float* bias;
    cudaGetSymbolAddress((void**)&qkvhi, g_qkvhi);
    cudaGetSymbolAddress((void**)&qkvlo, g_qkvlo);
    cudaGetSymbolAddress((void**)&ahi,   g_ahi);
    cudaGetSymbolAddress((void**)&alo,   g_alo);
    cudaGetSymbolAddress((void**)&whi,   g_whi);
    cudaGetSymbolAddress((void**)&wlo,   g_wlo);
    cudaGetSymbolAddress((void**)&bias,  g_bias);

    static int smem_set = 0;
    if (!smem_set) {
        cudaFuncSetAttribute(attn_tc_kernel,
                             cudaFuncAttributeMaxDynamicSharedMemorySize, A_SMEM);
        cudaFuncSetAttribute(gemm_fp16_split,
                             cudaFuncAttributeMaxDynamicSharedMemorySize, G_SMEM);
        smem_set = 1;
    }

    const int n4 = M * DMODEL / 4;

    split_kernel<<<(n4 + 255) / 256, 256>>>(x, ahi, alo, n4);
    conv_wqkv_kernel<<<(3 * DMODEL * 128) / 256, 256>>>(wq, wk, wv, bq, bk, bv,
                                                        whi, wlo, bias);
    // QKV projection: pass-3 only for Q,K columns (n0 < 2048)
    dim3 qkv_grid(3 * DMODEL / 128, M / 128);
    gemm_fp16_split<<<qkv_grid, 256, G_SMEM>>>(ahi, alo, whi, wlo, bias,
                                               (float*)nullptr, qkvhi, qkvlo,
                                               M, 2048);
    dim3 attn_grid(SQ / 128, NH, B);
    attn_tc_kernel<<<attn_grid, 128, A_SMEM>>>(qkvhi, qkvlo, ahi, alo);
    // Output projection: 2-pass (no W-lo)
    conv_wo_kernel<<<(DMODEL * 128) / 256, 256>>>(wo, whi);
    dim3 out_grid(DMODEL / 128, M / 128);
    gemm_fp16_split<<<out_grid, 256, G_SMEM>>>(ahi, alo, whi, whi,
                                               (const float*)nullptr,
                                               (float*)d_out, (__half*)nullptr,
                                               (__half*)nullptr, M, 0);
}